// round 3
// baseline (speedup 1.0000x reference)
#include <cuda_runtime.h>
#include <math.h>

#define IMG_H 2048
#define IMG_W 2048
#define HW (IMG_H * IMG_W)
#define THRESH 10.0f

// 180 / 3.14159 (reference uses this constant, NOT pi)
#define RAD2DEG_F 57.295827908797776f
#define RAD2DEG_D 57.29582790879777437539

__device__ __forceinline__ float ldz(const float* __restrict__ p, int y, int x) {
    return (y >= 0 && y < IMG_H && x >= 0 && x < IMG_W) ? __ldg(p + y * IMG_W + x) : 0.0f;
}

// ---------------------------------------------------------------------------
// Kernel 1: fused separable 5x5 Gaussian blur (zero pad), per channel.
// ---------------------------------------------------------------------------
__global__ void __launch_bounds__(256) blur_kernel(const float* __restrict__ img,
                                                   const float* __restrict__ g5,
                                                   float* __restrict__ out) {
    const int x  = blockIdx.x * 32 + threadIdx.x;
    const int y0 = (blockIdx.y * blockDim.y + threadIdx.y) * 4;
    const int c  = blockIdx.z;

    const float g0 = __ldg(g5 + 0), g1 = __ldg(g5 + 1), g2 = __ldg(g5 + 2),
                g3 = __ldg(g5 + 3), g4 = __ldg(g5 + 4);

    const float* __restrict__ src = img + c * HW;

    float hs[8];
#pragma unroll
    for (int j = 0; j < 8; j++) {
        const int r = y0 - 2 + j;
        float s = 0.0f;
        if (r >= 0 && r < IMG_H) {
            const float* row = src + r * IMG_W;
            s = g2 * __ldg(row + x);
            if (x >= 2)        s = fmaf(g0, __ldg(row + x - 2), s);
            if (x >= 1)        s = fmaf(g1, __ldg(row + x - 1), s);
            if (x + 1 < IMG_W) s = fmaf(g3, __ldg(row + x + 1), s);
            if (x + 2 < IMG_W) s = fmaf(g4, __ldg(row + x + 2), s);
        }
        hs[j] = s;
    }

    float* __restrict__ dst = out + c * HW;
#pragma unroll
    for (int k = 0; k < 4; k++) {
        const int y = y0 + k;
        float v = g0 * hs[k];
        v = fmaf(g1, hs[k + 1], v);
        v = fmaf(g2, hs[k + 2], v);
        v = fmaf(g3, hs[k + 3], v);
        v = fmaf(g4, hs[k + 4], v);
        dst[y * IMG_W + x] = v;
    }
}

// ---------------------------------------------------------------------------
// Exact (fp64) helpers. Integer-weight Sobel sums of fp32 values are exact in
// fp64; three double sqrts give ~1e-16 relative error, effectively exact.
// ---------------------------------------------------------------------------
__device__ __noinline__ void sobel_exact(const float* __restrict__ blurred,
                                         int y, int x, double& ogx, double& ogy,
                                         double& omag) {
    double gxs = 0.0, gys = 0.0, mg = 0.0;
#pragma unroll
    for (int c = 0; c < 3; c++) {
        const float* __restrict__ p = blurred + c * HW;
        const double a  = ldz(p, y - 1, x - 1);
        const double b  = ldz(p, y - 1, x    );
        const double cc = ldz(p, y - 1, x + 1);
        const double d  = ldz(p, y,     x - 1);
        const double e  = ldz(p, y,     x + 1);
        const double f  = ldz(p, y + 1, x - 1);
        const double g  = ldz(p, y + 1, x    );
        const double h  = ldz(p, y + 1, x + 1);
        const double gx = (a - cc) + 2.0 * (d - e) + (f - h);
        const double gy = (a + 2.0 * b + cc) - (f + 2.0 * g + h);
        gxs += gx; gys += gy;
        mg += sqrt(gx * gx + gy * gy);
    }
    ogx = gxs; ogy = gys; omag = mg;
}

__device__ __noinline__ int orient_k_exact(const float* __restrict__ blurred,
                                           int y, int x) {
    double gx, gy, m;
    sobel_exact(blurred, y, x, gx, gy, m);
    const double orient = atan2(gy, gx) * RAD2DEG_D + 180.0;
    return (int)rint(orient / 45.0);
}

// Exact grad_mag at a pixel (0 outside = zero-pad of the mag map).
__device__ __noinline__ double mag_exact(const float* __restrict__ blurred,
                                         int y, int x) {
    if (x < 0 || x >= IMG_W || y < 0 || y >= IMG_H) return 0.0;
    double gx, gy, m;
    sobel_exact(blurred, y, x, gx, gy, m);
    return m;
}

// ---------------------------------------------------------------------------
// Kernel 2: per-channel Sobel, grad magnitude, quantized orientation,
// early_threshold.
// ---------------------------------------------------------------------------
__global__ void __launch_bounds__(256) sobel_kernel(const float* __restrict__ blurred,
                                                    float* __restrict__ mag_out,
                                                    float* __restrict__ orient_out,
                                                    float* __restrict__ early_out) {
    const int x = blockIdx.x * blockDim.x + threadIdx.x;
    const int y = blockIdx.y * blockDim.y + threadIdx.y;

    float mag = 0.0f, sgx = 0.0f, sgy = 0.0f;
#pragma unroll
    for (int c = 0; c < 3; c++) {
        const float* __restrict__ p = blurred + c * HW;
        const float a  = ldz(p, y - 1, x - 1);
        const float b  = ldz(p, y - 1, x    );
        const float cc = ldz(p, y - 1, x + 1);
        const float d  = ldz(p, y,     x - 1);
        const float e  = ldz(p, y,     x + 1);
        const float f  = ldz(p, y + 1, x - 1);
        const float g  = ldz(p, y + 1, x    );
        const float h  = ldz(p, y + 1, x + 1);
        const float gx = (a - cc) + 2.0f * (d - e) + (f - h);
        const float gy = (a + 2.0f * b + cc) - (f + 2.0f * g + h);
        mag += sqrtf(gx * gx + gy * gy);
        sgx += gx;
        sgy += gy;
    }

    // Fast-path fp32 quantization; rescue near-boundary / near-branch-cut.
    const float t = (atan2f(sgy, sgx) * RAD2DEG_F + 180.0f) * (1.0f / 45.0f);
    int k = (int)rintf(t);
    const float dist = 0.5f - fabsf(t - (float)k);
    const bool near_cut = (sgx < 0.0f) && (fabsf(sgy) <= 1e-3f * fabsf(sgx));
    if (dist < 1e-3f || near_cut) {
        k = orient_k_exact(blurred, y, x);
    }

    const int idx = y * IMG_W + x;
    mag_out[idx]    = mag;
    orient_out[idx] = 45.0f * (float)k;
    early_out[idx]  = (mag < THRESH) ? 0.0f : mag;
}

// ---------------------------------------------------------------------------
// Kernel 3: directional NMS + threshold.
// dir d: 0:(0,+1) 1:(+1,+1) 2:(+1,0) 3:(+1,-1) 4:(0,-1) 5:(-1,-1) 6:(-1,0) 7:(-1,+1)
// Ties (|sel| within fp32 noise) are re-decided exactly in fp64.
// ---------------------------------------------------------------------------
__device__ const int c_dy[8] = { 0, 1, 1, 1, 0, -1, -1, -1 };
__device__ const int c_dx[8] = { 1, 1, 0, -1, -1, -1, 0, 1 };

__global__ void __launch_bounds__(256) nms_kernel(const float* __restrict__ mag,
                                                  const float* __restrict__ orient,
                                                  const float* __restrict__ blurred,
                                                  float* __restrict__ thin_out,
                                                  float* __restrict__ thresh_out) {
    const int x = blockIdx.x * blockDim.x + threadIdx.x;
    const int y = blockIdx.y * blockDim.y + threadIdx.y;
    const int idx = y * IMG_W + x;

    const float m = __ldg(mag + idx);
    const int k  = (int)rintf(__ldg(orient + idx) * (1.0f / 45.0f));
    const int ip = k & 7;
    const int in_ = (k + 4) & 7;

    const int py = y + c_dy[ip],  px = x + c_dx[ip];
    const int ny = y + c_dy[in_], nx = x + c_dx[in_];

    const float npos = ldz(mag, py, px);
    const float nneg = ldz(mag, ny, nx);

    const float sel_min = fminf(m - npos, m - nneg);

    bool is_max;
    const float eps = 4e-6f * fmaxf(m, 1.0f);
    if (fabsf(sel_min) > eps) {
        is_max = sel_min > 0.0f;
    } else {
        // Tie: decide with exact fp64 magnitudes.
        const double md = mag_exact(blurred, y, x);
        const double dp = md - mag_exact(blurred, py, px);
        const double dn = md - mag_exact(blurred, ny, nx);
        is_max = fmin(dp, dn) > 0.0;
    }

    const float thin = is_max ? m : 0.0f;
    thin_out[idx]   = thin;
    thresh_out[idx] = (thin < THRESH) ? 0.0f : thin;
}

// ---------------------------------------------------------------------------
// Output layout (concatenated reference tuple, fp32):
//   [0,3HW) blurred | [3HW,4HW) mag | [4HW,5HW) orient | [5HW,6HW) thin
//   [6HW,7HW) thresholded | [7HW,8HW) early
// ---------------------------------------------------------------------------
extern "C" void kernel_launch(void* const* d_in, const int* in_sizes, int n_in,
                              void* d_out, int out_size) {
    const float* img  = (const float*)d_in[0];
    const float* gh_w = (const float*)d_in[1];

    float* out       = (float*)d_out;
    float* blurred   = out;
    float* mag       = out + 3 * (size_t)HW;
    float* orient    = out + 4 * (size_t)HW;
    float* thin      = out + 5 * (size_t)HW;
    float* threshed  = out + 6 * (size_t)HW;
    float* early     = out + 7 * (size_t)HW;

    {
        dim3 block(32, 8, 1);
        dim3 grid(IMG_W / 32, IMG_H / 32, 3);
        blur_kernel<<<grid, block>>>(img, gh_w, blurred);
    }
    {
        dim3 block(32, 8, 1);
        dim3 grid(IMG_W / 32, IMG_H / 8, 1);
        sobel_kernel<<<grid, block>>>(blurred, mag, orient, early);
    }
    {
        dim3 block(32, 8, 1);
        dim3 grid(IMG_W / 32, IMG_H / 8, 1);
        nms_kernel<<<grid, block>>>(mag, orient, blurred, thin, threshed);
    }
}

// round 4
// speedup vs baseline: 1.0762x; 1.0762x over previous
#include <cuda_runtime.h>
#include <math.h>

#define IMG_H 2048
#define IMG_W 2048
#define HW (IMG_H * IMG_W)
#define THRESH 10.0f

// 180 / 3.14159 (reference uses this constant, NOT pi)
#define RAD2DEG_F 57.295827908797776f
#define RAD2DEG_D 57.29582790879777437539

// Tile: 32x32 outputs per block. Halo: +2 (blur->sobel) +1 (sobel->nms) +
// blur's own radius 2 => img tile 40x40, blurred 36x36, mag 34x34.

// ---------------------------------------------------------------------------
// Exact (fp64) helpers operating on the smem blurred tile (values are
// bit-identical to the global blurred map; zero outside the image).
// Integer-weight Sobel sums of fp32 values are exact in fp64.
// y, x are central-tile coords (0..31): image pos (by0+y, bx0+x) maps to
// sblur[c][y+2][x+2].
// ---------------------------------------------------------------------------
__device__ __noinline__ void sobel_exact_smem(const float (*sb)[36][36],
                                              int y, int x,
                                              double& ogx, double& ogy, double& omag) {
    double gxs = 0.0, gys = 0.0, mg = 0.0;
#pragma unroll
    for (int c = 0; c < 3; c++) {
        const double a  = sb[c][y + 1][x + 1];
        const double b  = sb[c][y + 1][x + 2];
        const double cc = sb[c][y + 1][x + 3];
        const double d  = sb[c][y + 2][x + 1];
        const double e  = sb[c][y + 2][x + 3];
        const double f  = sb[c][y + 3][x + 1];
        const double g  = sb[c][y + 3][x + 2];
        const double h  = sb[c][y + 3][x + 3];
        const double gx = (a - cc) + 2.0 * (d - e) + (f - h);
        const double gy = (a + 2.0 * b + cc) - (f + 2.0 * g + h);
        gxs += gx; gys += gy;
        mg += sqrt(gx * gx + gy * gy);
    }
    ogx = gxs; ogy = gys; omag = mg;
}

__device__ __noinline__ int orient_k_exact_smem(const float (*sb)[36][36],
                                                int y, int x) {
    double gx, gy, m;
    sobel_exact_smem(sb, y, x, gx, gy, m);
    const double orient = atan2(gy, gx) * RAD2DEG_D + 180.0;
    return (int)rint(orient / 45.0);
}

// Exact mag at central-coords (y,x) possibly offset outside the tile center
// (|dy|,|dx| <= 1); (Y,X) is the absolute image position (for the zero-pad test).
__device__ __noinline__ double mag_exact_smem(const float (*sb)[36][36],
                                              int y, int x, int Y, int X) {
    if (X < 0 || X >= IMG_W || Y < 0 || Y >= IMG_H) return 0.0;
    double gx, gy, m;
    sobel_exact_smem(sb, y, x, gx, gy, m);
    return m;
}

__global__ void __launch_bounds__(256)
canny_fused(const float* __restrict__ img,
            const float* __restrict__ g5,
            float* __restrict__ blurred_out,
            float* __restrict__ mag_out,
            float* __restrict__ orient_out,
            float* __restrict__ early_out,
            float* __restrict__ thin_out,
            float* __restrict__ thresh_out) {
    __shared__ float simg[40][40];
    __shared__ float hbuf[40][36];
    __shared__ float sblur[3][36][36];
    __shared__ float smag[34][34];
    __shared__ signed char sk[32][32];

    const int tx  = threadIdx.x;
    const int ty  = threadIdx.y;
    const int tid = ty * 32 + tx;
    const int bx0 = blockIdx.x * 32;
    const int by0 = blockIdx.y * 32;

    const float g0 = __ldg(g5 + 0), g1 = __ldg(g5 + 1), g2 = __ldg(g5 + 2),
                g3 = __ldg(g5 + 3), g4 = __ldg(g5 + 4);

    // ---------------- Stage A: blur each channel into sblur ----------------
    for (int c = 0; c < 3; c++) {
        const float* __restrict__ src = img + c * HW;
        // img tile origin (by0-4, bx0-4), zero-padded
        for (int i = tid; i < 40 * 40; i += 256) {
            const int r = i / 40, s = i % 40;
            const int Y = by0 - 4 + r, X = bx0 - 4 + s;
            float v = 0.0f;
            if (Y >= 0 && Y < IMG_H && X >= 0 && X < IMG_W)
                v = __ldg(src + Y * IMG_W + X);
            simg[r][s] = v;
        }
        __syncthreads();
        // horizontal pass: hbuf col s -> image col (bx0-2+s)
        for (int i = tid; i < 40 * 36; i += 256) {
            const int r = i / 36, s = i % 36;
            float v = g2 * simg[r][s + 2];
            v = fmaf(g0, simg[r][s],     v);
            v = fmaf(g1, simg[r][s + 1], v);
            v = fmaf(g3, simg[r][s + 3], v);
            v = fmaf(g4, simg[r][s + 4], v);
            hbuf[r][s] = v;
        }
        __syncthreads();
        // vertical pass: sblur[c][r][s] -> image pos (by0-2+r, bx0-2+s); 0 outside image
        for (int i = tid; i < 36 * 36; i += 256) {
            const int r = i / 36, s = i % 36;
            const int Y = by0 - 2 + r, X = bx0 - 2 + s;
            float v = 0.0f;
            if (Y >= 0 && Y < IMG_H && X >= 0 && X < IMG_W) {
                v = g0 * hbuf[r][s];
                v = fmaf(g1, hbuf[r + 1][s], v);
                v = fmaf(g2, hbuf[r + 2][s], v);
                v = fmaf(g3, hbuf[r + 3][s], v);
                v = fmaf(g4, hbuf[r + 4][s], v);
            }
            sblur[c][r][s] = v;
        }
        // write central 32x32 blurred output (smem already synced for sblur)
        __syncthreads();
#pragma unroll
        for (int k = 0; k < 4; k++) {
            const int y = ty + 8 * k;
            blurred_out[c * HW + (by0 + y) * IMG_W + (bx0 + tx)] =
                sblur[c][y + 2][tx + 2];
        }
        __syncthreads();  // before reusing simg/hbuf for next channel
    }

    // ---------------- Stage B: mag over 34x34 (tile +- 1) ----------------
    for (int i = tid; i < 34 * 34; i += 256) {
        const int r = i / 34, s = i % 34;
        const int Y = by0 - 1 + r, X = bx0 - 1 + s;
        float m = 0.0f;
        if (Y >= 0 && Y < IMG_H && X >= 0 && X < IMG_W) {
#pragma unroll
            for (int c = 0; c < 3; c++) {
                const float a  = sblur[c][r][s];
                const float b  = sblur[c][r][s + 1];
                const float cc = sblur[c][r][s + 2];
                const float d  = sblur[c][r + 1][s];
                const float e  = sblur[c][r + 1][s + 2];
                const float f  = sblur[c][r + 2][s];
                const float g  = sblur[c][r + 2][s + 1];
                const float h  = sblur[c][r + 2][s + 2];
                const float gx = (a - cc) + 2.0f * (d - e) + (f - h);
                const float gy = (a + 2.0f * b + cc) - (f + 2.0f * g + h);
                m += sqrtf(gx * gx + gy * gy);
            }
        }
        smag[r][s] = m;
    }
    __syncthreads();

    // ------- Stage C1: orientation per central pixel; write mag/orient/early -------
#pragma unroll
    for (int k = 0; k < 4; k++) {
        const int y = ty + 8 * k;
        const int Y = by0 + y, X = bx0 + tx;

        float sgx = 0.0f, sgy = 0.0f;
#pragma unroll
        for (int c = 0; c < 3; c++) {
            const float a  = sblur[c][y + 1][tx + 1];
            const float b  = sblur[c][y + 1][tx + 2];
            const float cc = sblur[c][y + 1][tx + 3];
            const float d  = sblur[c][y + 2][tx + 1];
            const float e  = sblur[c][y + 2][tx + 3];
            const float f  = sblur[c][y + 3][tx + 1];
            const float g  = sblur[c][y + 3][tx + 2];
            const float h  = sblur[c][y + 3][tx + 3];
            sgx += (a - cc) + 2.0f * (d - e) + (f - h);
            sgy += (a + 2.0f * b + cc) - (f + 2.0f * g + h);
        }

        const float t = (atan2f(sgy, sgx) * RAD2DEG_F + 180.0f) * (1.0f / 45.0f);
        int kq = (int)rintf(t);
        const float dist = 0.5f - fabsf(t - (float)kq);
        const bool near_cut = (sgx < 0.0f) && (fabsf(sgy) <= 1e-3f * fabsf(sgx));
        if (dist < 1e-3f || near_cut) {
            kq = orient_k_exact_smem(sblur, y, tx);
        }
        sk[y][tx] = (signed char)kq;

        const float m = smag[y + 1][tx + 1];
        const int idx = Y * IMG_W + X;
        mag_out[idx]    = m;
        orient_out[idx] = 45.0f * (float)kq;
        early_out[idx]  = (m < THRESH) ? 0.0f : m;
    }
    __syncthreads();

    // ---------------- Stage C2: NMS + threshold ----------------
    // dir d: 0:(0,+1) 1:(+1,+1) 2:(+1,0) 3:(+1,-1) 4:(0,-1) 5:(-1,-1) 6:(-1,0) 7:(-1,+1)
    const int dyt[8] = { 0, 1, 1, 1, 0, -1, -1, -1 };
    const int dxt[8] = { 1, 1, 0, -1, -1, -1, 0, 1 };

#pragma unroll
    for (int k = 0; k < 4; k++) {
        const int y = ty + 8 * k;
        const int Y = by0 + y, X = bx0 + tx;

        const float m = smag[y + 1][tx + 1];
        const int kq  = (int)sk[y][tx];
        const int ip  = kq & 7;
        const int in_ = (kq + 4) & 7;

        const int pdy = dyt[ip],  pdx = dxt[ip];
        const int ndy = dyt[in_], ndx = dxt[in_];

        const float npos = smag[y + 1 + pdy][tx + 1 + pdx];
        const float nneg = smag[y + 1 + ndy][tx + 1 + ndx];

        const float sel_min = fminf(m - npos, m - nneg);

        bool is_max;
        const float eps = 4e-6f * fmaxf(m, 1.0f);
        if (fabsf(sel_min) > eps) {
            is_max = sel_min > 0.0f;
        } else {
            const double md = mag_exact_smem(sblur, y, tx, Y, X);
            const double dp = md - mag_exact_smem(sblur, y + pdy, tx + pdx, Y + pdy, X + pdx);
            const double dn = md - mag_exact_smem(sblur, y + ndy, tx + ndx, Y + ndy, X + ndx);
            is_max = fmin(dp, dn) > 0.0;
        }

        const float thin = is_max ? m : 0.0f;
        const int idx = Y * IMG_W + X;
        thin_out[idx]   = thin;
        thresh_out[idx] = (thin < THRESH) ? 0.0f : thin;
    }
}

// ---------------------------------------------------------------------------
// Output layout (concatenated reference tuple, fp32):
//   [0,3HW) blurred | [3HW,4HW) mag | [4HW,5HW) orient | [5HW,6HW) thin
//   [6HW,7HW) thresholded | [7HW,8HW) early
// ---------------------------------------------------------------------------
extern "C" void kernel_launch(void* const* d_in, const int* in_sizes, int n_in,
                              void* d_out, int out_size) {
    const float* img  = (const float*)d_in[0];
    const float* gh_w = (const float*)d_in[1];

    float* out      = (float*)d_out;
    float* blurred  = out;
    float* mag      = out + 3 * (size_t)HW;
    float* orient   = out + 4 * (size_t)HW;
    float* thin     = out + 5 * (size_t)HW;
    float* threshed = out + 6 * (size_t)HW;
    float* early    = out + 7 * (size_t)HW;

    dim3 block(32, 8, 1);
    dim3 grid(IMG_W / 32, IMG_H / 32, 1);
    canny_fused<<<grid, block>>>(img, gh_w, blurred, mag, orient, early,
                                 thin, threshed);
}

// round 5
// speedup vs baseline: 1.1973x; 1.1125x over previous
#include <cuda_runtime.h>
#include <math.h>

#define IMG_H 2048
#define IMG_W 2048
#define HW (IMG_H * IMG_W)
#define THRESH 10.0f

// 180 / 3.14159 (reference uses this constant, NOT pi)
#define RAD2DEG_F 57.295827908797776f
#define RAD2DEG_D 57.29582790879777437539

// Tile: 32x32 outputs/block. hbuf 40x36 (h-blur), sblur 3x36x36, smag 34x34.
struct Smem {
    float hbuf[40][36];
    float sblur[3][36][36];
    float smag[34][34];
};

__device__ __forceinline__ float ldz_g(const float* __restrict__ p, int Y, int X) {
    return (Y >= 0 && Y < IMG_H && X >= 0 && X < IMG_W) ? __ldg(p + Y * IMG_W + X) : 0.0f;
}

// ---------------------------------------------------------------------------
// Exact (fp64) helpers on the smem blurred tile (bit-identical to the global
// blurred map; zero outside image). Integer-weight sums of fp32 are fp64-exact.
// (y,x) central-tile coords; image pos (by0+y, bx0+x) = sblur[c][y+2][x+2].
// ---------------------------------------------------------------------------
__device__ __noinline__ void sobel_exact_smem(const float (*sb)[36][36],
                                              int y, int x,
                                              double& ogx, double& ogy, double& omag) {
    double gxs = 0.0, gys = 0.0, mg = 0.0;
#pragma unroll
    for (int c = 0; c < 3; c++) {
        const double a  = sb[c][y + 1][x + 1];
        const double b  = sb[c][y + 1][x + 2];
        const double cc = sb[c][y + 1][x + 3];
        const double d  = sb[c][y + 2][x + 1];
        const double e  = sb[c][y + 2][x + 3];
        const double f  = sb[c][y + 3][x + 1];
        const double g  = sb[c][y + 3][x + 2];
        const double h  = sb[c][y + 3][x + 3];
        const double gx = (a - cc) + 2.0 * (d - e) + (f - h);
        const double gy = (a + 2.0 * b + cc) - (f + 2.0 * g + h);
        gxs += gx; gys += gy;
        mg += sqrt(gx * gx + gy * gy);
    }
    ogx = gxs; ogy = gys; omag = mg;
}

__device__ __noinline__ int orient_k_exact_smem(const float (*sb)[36][36],
                                                int y, int x) {
    double gx, gy, m;
    sobel_exact_smem(sb, y, x, gx, gy, m);
    const double orient = atan2(gy, gx) * RAD2DEG_D + 180.0;
    return (int)rint(orient / 45.0);
}

__device__ __noinline__ double mag_exact_smem(const float (*sb)[36][36],
                                              int y, int x, int Y, int X) {
    if (X < 0 || X >= IMG_W || Y < 0 || Y >= IMG_H) return 0.0;
    double gx, gy, m;
    sobel_exact_smem(sb, y, x, gx, gy, m);
    return m;
}

// Packed direction tables (value+1 in nibbles, dir d at nibble 4d):
// dx: d0..d7 = +1,+1,0,-1,-1,-1,0,+1 -> 0x21000122
// dy: d0..d7 =  0,+1,+1,+1,0,-1,-1,-1 -> 0x00012221
#define DX_PACK 0x21000122u
#define DY_PACK 0x00012221u
__device__ __forceinline__ int unpack_d(unsigned pack, int d) {
    return (int)((pack >> (4 * d)) & 0xFu) - 1;
}

template <bool BORDER>
__device__ __forceinline__ void canny_body(
    Smem& sm, const float* __restrict__ img,
    float g0, float g1, float g2, float g3, float g4,
    int bx0, int by0, int tx, int ty,
    float* __restrict__ blurred_out, float* __restrict__ mag_out,
    float* __restrict__ orient_out, float* __restrict__ early_out,
    float* __restrict__ thin_out, float* __restrict__ thresh_out) {

    // ---------------- Stage A: blur each channel into sblur ----------------
    for (int c = 0; c < 3; c++) {
        const float* __restrict__ src = img + c * HW;

        // h-pass: hbuf[r][s] = hsum at image (by0-4+r, bx0-2+s)
#pragma unroll
        for (int j = 0; j < 5; j++) {
            const int r = ty + 8 * j;           // 0..39
            const int Y = by0 - 4 + r;
#pragma unroll
            for (int grp = 0; grp < 2; grp++) {
                const int s = grp ? (32 + tx) : tx;
                if (grp == 0 || tx < 4) {
                    const int X0 = bx0 - 4 + s;
                    float x0, x1, x2, x3, x4;
                    if (BORDER) {
                        x0 = ldz_g(src, Y, X0);     x1 = ldz_g(src, Y, X0 + 1);
                        x2 = ldz_g(src, Y, X0 + 2); x3 = ldz_g(src, Y, X0 + 3);
                        x4 = ldz_g(src, Y, X0 + 4);
                    } else {
                        const float* row = src + Y * IMG_W + X0;
                        x0 = __ldg(row);     x1 = __ldg(row + 1);
                        x2 = __ldg(row + 2); x3 = __ldg(row + 3);
                        x4 = __ldg(row + 4);
                    }
                    float v = g2 * x2;
                    v = fmaf(g0, x0, v);
                    v = fmaf(g1, x1, v);
                    v = fmaf(g3, x3, v);
                    v = fmaf(g4, x4, v);
                    sm.hbuf[r][s] = v;
                }
            }
        }
        __syncthreads();

        // v-pass: sblur[c][r][s] at image (by0-2+r, bx0-2+s); 0 outside image.
#pragma unroll
        for (int j = 0; j < 5; j++) {
            const int r = ty + 8 * j;           // need r < 36
            if (j < 4 || ty < 4) {
#pragma unroll
                for (int grp = 0; grp < 2; grp++) {
                    const int s = grp ? (32 + tx) : tx;
                    if (grp == 0 || tx < 4) {
                        float v;
                        if (BORDER) {
                            const int Y = by0 - 2 + r, X = bx0 - 2 + s;
                            if (Y < 0 || Y >= IMG_H || X < 0 || X >= IMG_W) {
                                v = 0.0f;
                            } else {
                                v = g0 * sm.hbuf[r][s];
                                v = fmaf(g1, sm.hbuf[r + 1][s], v);
                                v = fmaf(g2, sm.hbuf[r + 2][s], v);
                                v = fmaf(g3, sm.hbuf[r + 3][s], v);
                                v = fmaf(g4, sm.hbuf[r + 4][s], v);
                            }
                        } else {
                            v = g0 * sm.hbuf[r][s];
                            v = fmaf(g1, sm.hbuf[r + 1][s], v);
                            v = fmaf(g2, sm.hbuf[r + 2][s], v);
                            v = fmaf(g3, sm.hbuf[r + 3][s], v);
                            v = fmaf(g4, sm.hbuf[r + 4][s], v);
                        }
                        sm.sblur[c][r][s] = v;
                    }
                }
            }
        }
        __syncthreads();

        // write central 32x32 blurred output (sblur synced)
#pragma unroll
        for (int k = 0; k < 4; k++) {
            const int y = ty + 8 * k;
            blurred_out[c * HW + (by0 + y) * IMG_W + (bx0 + tx)] =
                sm.sblur[c][y + 2][tx + 2];
        }
        // no barrier needed: next h-pass writes hbuf (reads finished pre-sync)
    }

    // ---------------- Stage B: mag over 34x34 (tile +- 1) ----------------
#pragma unroll
    for (int j = 0; j < 5; j++) {
        const int r = ty + 8 * j;               // need r < 34
        if (j < 4 || ty < 2) {
#pragma unroll
            for (int grp = 0; grp < 2; grp++) {
                const int s = grp ? (32 + tx) : tx;
                if (grp == 0 || tx < 2) {
                    float m = 0.0f;
                    bool ok = true;
                    if (BORDER) {
                        const int Y = by0 - 1 + r, X = bx0 - 1 + s;
                        ok = (Y >= 0 && Y < IMG_H && X >= 0 && X < IMG_W);
                    }
                    if (ok) {
#pragma unroll
                        for (int c = 0; c < 3; c++) {
                            const float a  = sm.sblur[c][r][s];
                            const float b  = sm.sblur[c][r][s + 1];
                            const float cc = sm.sblur[c][r][s + 2];
                            const float d  = sm.sblur[c][r + 1][s];
                            const float e  = sm.sblur[c][r + 1][s + 2];
                            const float f  = sm.sblur[c][r + 2][s];
                            const float g  = sm.sblur[c][r + 2][s + 1];
                            const float h  = sm.sblur[c][r + 2][s + 2];
                            const float gx = (a - cc) + 2.0f * (d - e) + (f - h);
                            const float gy = (a + 2.0f * b + cc) - (f + 2.0f * g + h);
                            m += sqrtf(gx * gx + gy * gy);
                        }
                    }
                    sm.smag[r][s] = m;
                }
            }
        }
    }
    __syncthreads();

    // ------- Stage C: orientation + NMS + all remaining outputs -------
#pragma unroll
    for (int k = 0; k < 4; k++) {
        const int y = ty + 8 * k;
        const int Y = by0 + y, X = bx0 + tx;

        float sgx = 0.0f, sgy = 0.0f;
#pragma unroll
        for (int c = 0; c < 3; c++) {
            const float a  = sm.sblur[c][y + 1][tx + 1];
            const float b  = sm.sblur[c][y + 1][tx + 2];
            const float cc = sm.sblur[c][y + 1][tx + 3];
            const float d  = sm.sblur[c][y + 2][tx + 1];
            const float e  = sm.sblur[c][y + 2][tx + 3];
            const float f  = sm.sblur[c][y + 3][tx + 1];
            const float g  = sm.sblur[c][y + 3][tx + 2];
            const float h  = sm.sblur[c][y + 3][tx + 3];
            sgx += (a - cc) + 2.0f * (d - e) + (f - h);
            sgy += (a + 2.0f * b + cc) - (f + 2.0f * g + h);
        }

        const float t = (atan2f(sgy, sgx) * RAD2DEG_F + 180.0f) * (1.0f / 45.0f);
        int kq = (int)rintf(t);
        const float dist = 0.5f - fabsf(t - (float)kq);
        const bool near_cut = (sgx < 0.0f) && (fabsf(sgy) <= 1e-3f * fabsf(sgx));
        if (dist < 1e-3f || near_cut) {
            kq = orient_k_exact_smem(sm.sblur, y, tx);
        }

        const float m = sm.smag[y + 1][tx + 1];
        const int idx = Y * IMG_W + X;
        mag_out[idx]    = m;
        orient_out[idx] = 45.0f * (float)kq;
        early_out[idx]  = (m < THRESH) ? 0.0f : m;

        // NMS
        const int ip  = kq & 7;
        const int in_ = (kq + 4) & 7;
        const int pdy = unpack_d(DY_PACK, ip),  pdx = unpack_d(DX_PACK, ip);
        const int ndy = unpack_d(DY_PACK, in_), ndx = unpack_d(DX_PACK, in_);

        const float npos = sm.smag[y + 1 + pdy][tx + 1 + pdx];
        const float nneg = sm.smag[y + 1 + ndy][tx + 1 + ndx];
        const float sel_min = fminf(m - npos, m - nneg);

        bool is_max;
        const float eps = 4e-6f * fmaxf(m, 1.0f);
        if (fabsf(sel_min) > eps) {
            is_max = sel_min > 0.0f;
        } else {
            const double md = mag_exact_smem(sm.sblur, y, tx, Y, X);
            const double dp = md - mag_exact_smem(sm.sblur, y + pdy, tx + pdx, Y + pdy, X + pdx);
            const double dn = md - mag_exact_smem(sm.sblur, y + ndy, tx + ndx, Y + ndy, X + ndx);
            is_max = fmin(dp, dn) > 0.0;
        }

        const float thin = is_max ? m : 0.0f;
        thin_out[idx]   = thin;
        thresh_out[idx] = (thin < THRESH) ? 0.0f : thin;
    }
}

__global__ void __launch_bounds__(256)
canny_fused(const float* __restrict__ img,
            const float* __restrict__ g5,
            float* __restrict__ blurred_out,
            float* __restrict__ mag_out,
            float* __restrict__ orient_out,
            float* __restrict__ early_out,
            float* __restrict__ thin_out,
            float* __restrict__ thresh_out) {
    __shared__ Smem sm;

    const int tx  = threadIdx.x;
    const int ty  = threadIdx.y;
    const int bx0 = blockIdx.x * 32;
    const int by0 = blockIdx.y * 32;

    const float g0 = __ldg(g5 + 0), g1 = __ldg(g5 + 1), g2 = __ldg(g5 + 2),
                g3 = __ldg(g5 + 3), g4 = __ldg(g5 + 4);

    // Interior block: all stencil accesses [bx0-4, bx0+36) x [by0-4, by0+36)
    // are strictly inside the image.
    const bool interior = (bx0 != 0) && (bx0 != IMG_W - 32) &&
                          (by0 != 0) && (by0 != IMG_H - 32);
    if (interior) {
        canny_body<false>(sm, img, g0, g1, g2, g3, g4, bx0, by0, tx, ty,
                          blurred_out, mag_out, orient_out, early_out,
                          thin_out, thresh_out);
    } else {
        canny_body<true>(sm, img, g0, g1, g2, g3, g4, bx0, by0, tx, ty,
                         blurred_out, mag_out, orient_out, early_out,
                         thin_out, thresh_out);
    }
}

// ---------------------------------------------------------------------------
// Output layout (concatenated reference tuple, fp32):
//   [0,3HW) blurred | [3HW,4HW) mag | [4HW,5HW) orient | [5HW,6HW) thin
//   [6HW,7HW) thresholded | [7HW,8HW) early
// ---------------------------------------------------------------------------
extern "C" void kernel_launch(void* const* d_in, const int* in_sizes, int n_in,
                              void* d_out, int out_size) {
    const float* img  = (const float*)d_in[0];
    const float* gh_w = (const float*)d_in[1];

    float* out      = (float*)d_out;
    float* blurred  = out;
    float* mag      = out + 3 * (size_t)HW;
    float* orient   = out + 4 * (size_t)HW;
    float* thin     = out + 5 * (size_t)HW;
    float* threshed = out + 6 * (size_t)HW;
    float* early    = out + 7 * (size_t)HW;

    dim3 block(32, 8, 1);
    dim3 grid(IMG_W / 32, IMG_H / 32, 1);
    canny_fused<<<grid, block>>>(img, gh_w, blurred, mag, orient, early,
                                 thin, threshed);
}

// round 6
// speedup vs baseline: 1.2431x; 1.0383x over previous
#include <cuda_runtime.h>
#include <math.h>

#define IMG_H 2048
#define IMG_W 2048
#define HW (IMG_H * IMG_W)
#define THRESH 10.0f

// 180 / 3.14159 (reference uses this constant, NOT pi)
#define RAD2DEG_F 57.295827908797776f
#define RAD2DEG_D 57.29582790879777437539

// Tile: 32x32 outputs/block. hbuf 40x36 (h-blur, later reused as sk),
// sblur 3x36x36, smag 34x34.
struct Smem {
    union {
        float hbuf[40][36];
        signed char sk[32][32];
    } u;
    float sblur[3][36][36];
    float smag[34][34];
};

__device__ __forceinline__ float ldz_g(const float* __restrict__ p, int Y, int X) {
    return (Y >= 0 && Y < IMG_H && X >= 0 && X < IMG_W) ? __ldg(p + Y * IMG_W + X) : 0.0f;
}

// ---------------------------------------------------------------------------
// Exact (fp64) helpers on the smem blurred tile (bit-identical to the global
// blurred map; zero outside image). Integer-weight sums of fp32 are fp64-exact.
// (y,x) central-tile coords; image pos (by0+y, bx0+x) = sblur[c][y+2][x+2].
// ---------------------------------------------------------------------------
__device__ __noinline__ void sobel_exact_smem(const float (*sb)[36][36],
                                              int y, int x,
                                              double& ogx, double& ogy, double& omag) {
    double gxs = 0.0, gys = 0.0, mg = 0.0;
#pragma unroll
    for (int c = 0; c < 3; c++) {
        const double a  = sb[c][y + 1][x + 1];
        const double b  = sb[c][y + 1][x + 2];
        const double cc = sb[c][y + 1][x + 3];
        const double d  = sb[c][y + 2][x + 1];
        const double e  = sb[c][y + 2][x + 3];
        const double f  = sb[c][y + 3][x + 1];
        const double g  = sb[c][y + 3][x + 2];
        const double h  = sb[c][y + 3][x + 3];
        const double gx = (a - cc) + 2.0 * (d - e) + (f - h);
        const double gy = (a + 2.0 * b + cc) - (f + 2.0 * g + h);
        gxs += gx; gys += gy;
        mg += sqrt(gx * gx + gy * gy);
    }
    ogx = gxs; ogy = gys; omag = mg;
}

__device__ __noinline__ int orient_k_exact_smem(const float (*sb)[36][36],
                                                int y, int x) {
    double gx, gy, m;
    sobel_exact_smem(sb, y, x, gx, gy, m);
    const double orient = atan2(gy, gx) * RAD2DEG_D + 180.0;
    return (int)rint(orient / 45.0);
}

__device__ __noinline__ double mag_exact_smem(const float (*sb)[36][36],
                                              int y, int x, int Y, int X) {
    if (X < 0 || X >= IMG_W || Y < 0 || Y >= IMG_H) return 0.0;
    double gx, gy, m;
    sobel_exact_smem(sb, y, x, gx, gy, m);
    return m;
}

// Packed direction tables (value+1 in nibbles, dir d at nibble 4d):
// dx: d0..d7 = +1,+1,0,-1,-1,-1,0,+1 -> 0x21000122
// dy: d0..d7 =  0,+1,+1,+1,0,-1,-1,-1 -> 0x00012221
#define DX_PACK 0x21000122u
#define DY_PACK 0x00012221u
__device__ __forceinline__ int unpack_d(unsigned pack, int d) {
    return (int)((pack >> (4 * d)) & 0xFu) - 1;
}

template <bool BORDER>
__device__ __forceinline__ void canny_body(
    Smem& sm, const float* __restrict__ img,
    float g0, float g1, float g2, float g3, float g4,
    int bx0, int by0, int tx, int ty,
    float* __restrict__ blurred_out, float* __restrict__ mag_out,
    float* __restrict__ orient_out, float* __restrict__ early_out,
    float* __restrict__ thin_out, float* __restrict__ thresh_out) {

    // ---------------- Stage A: blur each channel into sblur ----------------
    for (int c = 0; c < 3; c++) {
        const float* __restrict__ src = img + c * HW;

        // h-pass: hbuf[r][s] = hsum at image (by0-4+r, bx0-2+s)
#pragma unroll
        for (int j = 0; j < 5; j++) {
            const int r = ty + 8 * j;           // 0..39
            const int Y = by0 - 4 + r;
#pragma unroll
            for (int grp = 0; grp < 2; grp++) {
                const int s = grp ? (32 + tx) : tx;
                if (grp == 0 || tx < 4) {
                    const int X0 = bx0 - 4 + s;
                    float x0, x1, x2, x3, x4;
                    if (BORDER) {
                        x0 = ldz_g(src, Y, X0);     x1 = ldz_g(src, Y, X0 + 1);
                        x2 = ldz_g(src, Y, X0 + 2); x3 = ldz_g(src, Y, X0 + 3);
                        x4 = ldz_g(src, Y, X0 + 4);
                    } else {
                        const float* row = src + Y * IMG_W + X0;
                        x0 = __ldg(row);     x1 = __ldg(row + 1);
                        x2 = __ldg(row + 2); x3 = __ldg(row + 3);
                        x4 = __ldg(row + 4);
                    }
                    float v = g2 * x2;
                    v = fmaf(g0, x0, v);
                    v = fmaf(g1, x1, v);
                    v = fmaf(g3, x3, v);
                    v = fmaf(g4, x4, v);
                    sm.u.hbuf[r][s] = v;
                }
            }
        }
        __syncthreads();

        // v-pass: sblur[c][r][s] at image (by0-2+r, bx0-2+s); 0 outside image.
#pragma unroll
        for (int j = 0; j < 5; j++) {
            const int r = ty + 8 * j;           // need r < 36
            if (j < 4 || ty < 4) {
#pragma unroll
                for (int grp = 0; grp < 2; grp++) {
                    const int s = grp ? (32 + tx) : tx;
                    if (grp == 0 || tx < 4) {
                        float v;
                        if (BORDER) {
                            const int Y = by0 - 2 + r, X = bx0 - 2 + s;
                            if (Y < 0 || Y >= IMG_H || X < 0 || X >= IMG_W) {
                                v = 0.0f;
                            } else {
                                v = g0 * sm.u.hbuf[r][s];
                                v = fmaf(g1, sm.u.hbuf[r + 1][s], v);
                                v = fmaf(g2, sm.u.hbuf[r + 2][s], v);
                                v = fmaf(g3, sm.u.hbuf[r + 3][s], v);
                                v = fmaf(g4, sm.u.hbuf[r + 4][s], v);
                            }
                        } else {
                            v = g0 * sm.u.hbuf[r][s];
                            v = fmaf(g1, sm.u.hbuf[r + 1][s], v);
                            v = fmaf(g2, sm.u.hbuf[r + 2][s], v);
                            v = fmaf(g3, sm.u.hbuf[r + 3][s], v);
                            v = fmaf(g4, sm.u.hbuf[r + 4][s], v);
                        }
                        sm.sblur[c][r][s] = v;
                    }
                }
            }
        }
        __syncthreads();

        // write central 32x32 blurred output (sblur synced)
#pragma unroll
        for (int k = 0; k < 4; k++) {
            const int y = ty + 8 * k;
            blurred_out[c * HW + (by0 + y) * IMG_W + (bx0 + tx)] =
                sm.sblur[c][y + 2][tx + 2];
        }
        // no barrier needed before next h-pass: hbuf reads completed pre-sync
    }

    // ------- Stage B: mag over 34x34; orientation for central 32x32 -------
    // (hbuf is dead; its storage now holds sk.)
#pragma unroll
    for (int j = 0; j < 5; j++) {
        const int r = ty + 8 * j;               // need r < 34
        if (j < 4 || ty < 2) {
#pragma unroll
            for (int grp = 0; grp < 2; grp++) {
                const int s = grp ? (32 + tx) : tx;
                if (grp == 0 || tx < 2) {
                    float m = 0.0f, sgx = 0.0f, sgy = 0.0f;
                    bool ok = true;
                    if (BORDER) {
                        const int Y = by0 - 1 + r, X = bx0 - 1 + s;
                        ok = (Y >= 0 && Y < IMG_H && X >= 0 && X < IMG_W);
                    }
                    if (ok) {
#pragma unroll
                        for (int c = 0; c < 3; c++) {
                            const float a  = sm.sblur[c][r][s];
                            const float b  = sm.sblur[c][r][s + 1];
                            const float cc = sm.sblur[c][r][s + 2];
                            const float d  = sm.sblur[c][r + 1][s];
                            const float e  = sm.sblur[c][r + 1][s + 2];
                            const float f  = sm.sblur[c][r + 2][s];
                            const float g  = sm.sblur[c][r + 2][s + 1];
                            const float h  = sm.sblur[c][r + 2][s + 2];
                            const float gx = (a - cc) + 2.0f * (d - e) + (f - h);
                            const float gy = (a + 2.0f * b + cc) - (f + 2.0f * g + h);
                            m += sqrtf(gx * gx + gy * gy);
                            sgx += gx;
                            sgy += gy;
                        }
                    }
                    sm.smag[r][s] = m;

                    // orientation only for central pixels
                    if (r >= 1 && r < 33 && s >= 1 && s < 33) {
                        const float t =
                            (atan2f(sgy, sgx) * RAD2DEG_F + 180.0f) * (1.0f / 45.0f);
                        int kq = (int)rintf(t);
                        const float dist = 0.5f - fabsf(t - (float)kq);
                        const bool near_cut =
                            (sgx < 0.0f) && (fabsf(sgy) <= 1e-3f * fabsf(sgx));
                        if (dist < 1e-3f || near_cut) {
                            kq = orient_k_exact_smem(sm.sblur, r - 1, s - 1);
                        }
                        sm.u.sk[r - 1][s - 1] = (signed char)kq;
                    }
                }
            }
        }
    }
    __syncthreads();

    // ------- Stage C: NMS + write mag/orient/early/thin/thresh -------
#pragma unroll
    for (int k = 0; k < 4; k++) {
        const int y = ty + 8 * k;
        const int Y = by0 + y, X = bx0 + tx;

        const float m = sm.smag[y + 1][tx + 1];
        const int kq  = (int)sm.u.sk[y][tx];

        const int idx = Y * IMG_W + X;
        mag_out[idx]    = m;
        orient_out[idx] = 45.0f * (float)kq;
        early_out[idx]  = (m < THRESH) ? 0.0f : m;

        const int ip  = kq & 7;
        const int in_ = (kq + 4) & 7;
        const int pdy = unpack_d(DY_PACK, ip),  pdx = unpack_d(DX_PACK, ip);
        const int ndy = unpack_d(DY_PACK, in_), ndx = unpack_d(DX_PACK, in_);

        const float npos = sm.smag[y + 1 + pdy][tx + 1 + pdx];
        const float nneg = sm.smag[y + 1 + ndy][tx + 1 + ndx];
        const float sel_min = fminf(m - npos, m - nneg);

        bool is_max;
        const float eps = 4e-6f * fmaxf(m, 1.0f);
        if (fabsf(sel_min) > eps) {
            is_max = sel_min > 0.0f;
        } else {
            const double md = mag_exact_smem(sm.sblur, y, tx, Y, X);
            const double dp = md - mag_exact_smem(sm.sblur, y + pdy, tx + pdx, Y + pdy, X + pdx);
            const double dn = md - mag_exact_smem(sm.sblur, y + ndy, tx + ndx, Y + ndy, X + ndx);
            is_max = fmin(dp, dn) > 0.0;
        }

        const float thin = is_max ? m : 0.0f;
        thin_out[idx]   = thin;
        thresh_out[idx] = (thin < THRESH) ? 0.0f : thin;
    }
}

__global__ void __launch_bounds__(256, 5)
canny_fused(const float* __restrict__ img,
            const float* __restrict__ g5,
            float* __restrict__ blurred_out,
            float* __restrict__ mag_out,
            float* __restrict__ orient_out,
            float* __restrict__ early_out,
            float* __restrict__ thin_out,
            float* __restrict__ thresh_out) {
    __shared__ Smem sm;

    const int tx  = threadIdx.x;
    const int ty  = threadIdx.y;
    const int bx0 = blockIdx.x * 32;
    const int by0 = blockIdx.y * 32;

    const float g0 = __ldg(g5 + 0), g1 = __ldg(g5 + 1), g2 = __ldg(g5 + 2),
                g3 = __ldg(g5 + 3), g4 = __ldg(g5 + 4);

    const bool interior = (bx0 != 0) && (bx0 != IMG_W - 32) &&
                          (by0 != 0) && (by0 != IMG_H - 32);
    if (interior) {
        canny_body<false>(sm, img, g0, g1, g2, g3, g4, bx0, by0, tx, ty,
                          blurred_out, mag_out, orient_out, early_out,
                          thin_out, thresh_out);
    } else {
        canny_body<true>(sm, img, g0, g1, g2, g3, g4, bx0, by0, tx, ty,
                         blurred_out, mag_out, orient_out, early_out,
                         thin_out, thresh_out);
    }
}

// ---------------------------------------------------------------------------
// Output layout (concatenated reference tuple, fp32):
//   [0,3HW) blurred | [3HW,4HW) mag | [4HW,5HW) orient | [5HW,6HW) thin
//   [6HW,7HW) thresholded | [7HW,8HW) early
// ---------------------------------------------------------------------------
extern "C" void kernel_launch(void* const* d_in, const int* in_sizes, int n_in,
                              void* d_out, int out_size) {
    const float* img  = (const float*)d_in[0];
    const float* gh_w = (const float*)d_in[1];

    float* out      = (float*)d_out;
    float* blurred  = out;
    float* mag      = out + 3 * (size_t)HW;
    float* orient   = out + 4 * (size_t)HW;
    float* thin     = out + 5 * (size_t)HW;
    float* threshed = out + 6 * (size_t)HW;
    float* early    = out + 7 * (size_t)HW;

    dim3 block(32, 8, 1);
    dim3 grid(IMG_W / 32, IMG_H / 32, 1);
    canny_fused<<<grid, block>>>(img, gh_w, blurred, mag, orient, early,
                                 thin, threshed);
}

// round 7
// speedup vs baseline: 1.2835x; 1.0325x over previous
#include <cuda_runtime.h>
#include <math.h>

#define IMG_H 2048
#define IMG_W 2048
#define HW (IMG_H * IMG_W)
#define THRESH 10.0f

// 180 / 3.14159 (reference constant, NOT pi)
#define RAD2DEG_D 57.29582790879777437539

// Octant boundary tangents for k = round((atan2*R+180)/45), R=180/3.14159.
// Boundaries in true radians: gx>=0 side at w/2, 3w/2 (w = 3.14159/4);
// gx<0 side at pi-7w/2, pi-5w/2 (measured from -x axis).
#define T1_POS 0.41421317376f   // tan(w/2)
#define T2_POS 2.41420677f      // tan(3w/2)
#define T1_NEG 0.41421628f      // tan(pi - 7w/2)
#define T2_NEG 2.41422489f      // tan(pi - 5w/2)
// risk bands ~ 7.85e-4 rad * sec^2(boundary), with margin
#define BAND1 1.0e-3f
#define BAND2 6.0e-3f

// smem: hbuf (h-blur staging, 3ch) unioned with {smag, sk} used later.
struct Smem {
    union {
        float hbuf[3][40][36];
        struct {
            float smag[34][34];
            signed char sk[32][32];
        } b;
    } u;
    float sblur[3][36][36];
};

__device__ __forceinline__ float ldz_g(const float* __restrict__ p, int Y, int X) {
    return (Y >= 0 && Y < IMG_H && X >= 0 && X < IMG_W) ? __ldg(p + Y * IMG_W + X) : 0.0f;
}

__device__ __forceinline__ float sqrt_approx(float x) {
    float r;
    asm("sqrt.approx.f32 %0, %1;" : "=f"(r) : "f"(x));
    return r;
}

// ---------------------------------------------------------------------------
// Exact (fp64) helpers on the smem blurred tile (bit-identical to the global
// blurred map; zero outside image). Integer-weight sums of fp32 are fp64-exact.
// (y,x) central coords: image (by0+y, bx0+x) = sblur[c][y+2][x+2].
// ---------------------------------------------------------------------------
__device__ __noinline__ void sobel_exact_smem(const float (*sb)[36][36],
                                              int y, int x,
                                              double& ogx, double& ogy, double& omag) {
    double gxs = 0.0, gys = 0.0, mg = 0.0;
#pragma unroll
    for (int c = 0; c < 3; c++) {
        const double a  = sb[c][y + 1][x + 1];
        const double b  = sb[c][y + 1][x + 2];
        const double cc = sb[c][y + 1][x + 3];
        const double d  = sb[c][y + 2][x + 1];
        const double e  = sb[c][y + 2][x + 3];
        const double f  = sb[c][y + 3][x + 1];
        const double g  = sb[c][y + 3][x + 2];
        const double h  = sb[c][y + 3][x + 3];
        const double gx = (a - cc) + 2.0 * (d - e) + (f - h);
        const double gy = (a + 2.0 * b + cc) - (f + 2.0 * g + h);
        gxs += gx; gys += gy;
        mg += sqrt(gx * gx + gy * gy);
    }
    ogx = gxs; ogy = gys; omag = mg;
}

__device__ __noinline__ int orient_k_exact_smem(const float (*sb)[36][36],
                                                int y, int x) {
    double gx, gy, m;
    sobel_exact_smem(sb, y, x, gx, gy, m);
    const double orient = atan2(gy, gx) * RAD2DEG_D + 180.0;
    return (int)rint(orient / 45.0);
}

__device__ __noinline__ double mag_exact_smem(const float (*sb)[36][36],
                                              int y, int x, int Y, int X) {
    if (X < 0 || X >= IMG_W || Y < 0 || Y >= IMG_H) return 0.0;
    double gx, gy, m;
    sobel_exact_smem(sb, y, x, gx, gy, m);
    return m;
}

// Packed direction tables (value+1 in nibbles, dir d at nibble 4d):
// dx: d0..d7 = +1,+1,0,-1,-1,-1,0,+1 -> 0x21000122
// dy: d0..d7 =  0,+1,+1,+1,0,-1,-1,-1 -> 0x00012221
#define DX_PACK 0x21000122u
#define DY_PACK 0x00012221u
__device__ __forceinline__ int unpack_d(unsigned pack, int d) {
    return (int)((pack >> (4 * d)) & 0xFu) - 1;
}

template <bool BORDER>
__device__ __forceinline__ void canny_body(
    Smem& sm, const float* __restrict__ img,
    float g0, float g1, float g2, float g3, float g4,
    int bx0, int by0, int tx, int ty,
    float* __restrict__ blurred_out, float* __restrict__ mag_out,
    float* __restrict__ orient_out, float* __restrict__ early_out,
    float* __restrict__ thin_out, float* __restrict__ thresh_out) {

    // ---- Stage A1: horizontal blur, all 3 channels ----
    // hbuf[c][r][s] = hsum at image (by0-4+r, bx0-2+s)
#pragma unroll
    for (int j = 0; j < 5; j++) {
        const int r = ty + 8 * j;               // 0..39
        const int Y = by0 - 4 + r;
#pragma unroll
        for (int grp = 0; grp < 2; grp++) {
            const int s = grp ? (32 + tx) : tx;
            if (grp == 0 || tx < 4) {
                const int X0 = bx0 - 4 + s;
#pragma unroll
                for (int c = 0; c < 3; c++) {
                    const float* __restrict__ src = img + c * HW;
                    float x0, x1, x2, x3, x4;
                    if (BORDER) {
                        x0 = ldz_g(src, Y, X0);     x1 = ldz_g(src, Y, X0 + 1);
                        x2 = ldz_g(src, Y, X0 + 2); x3 = ldz_g(src, Y, X0 + 3);
                        x4 = ldz_g(src, Y, X0 + 4);
                    } else {
                        const float* row = src + Y * IMG_W + X0;
                        x0 = __ldg(row);     x1 = __ldg(row + 1);
                        x2 = __ldg(row + 2); x3 = __ldg(row + 3);
                        x4 = __ldg(row + 4);
                    }
                    float v = g2 * x2;
                    v = fmaf(g0, x0, v);
                    v = fmaf(g1, x1, v);
                    v = fmaf(g3, x3, v);
                    v = fmaf(g4, x4, v);
                    sm.u.hbuf[c][r][s] = v;
                }
            }
        }
    }
    __syncthreads();

    // ---- Stage A2: vertical blur, all channels; direct blurred_out write ----
    // sblur[c][r][s] at image (by0-2+r, bx0-2+s); 0 outside image.
#pragma unroll
    for (int j = 0; j < 5; j++) {
        const int r = ty + 8 * j;               // need r < 36
        if (j < 4 || ty < 4) {
#pragma unroll
            for (int grp = 0; grp < 2; grp++) {
                const int s = grp ? (32 + tx) : tx;
                if (grp == 0 || tx < 4) {
                    const bool central = (r >= 2) && (r < 34) && (s >= 2) && (s < 34);
#pragma unroll
                    for (int c = 0; c < 3; c++) {
                        float v;
                        if (BORDER) {
                            const int Y = by0 - 2 + r, X = bx0 - 2 + s;
                            if (Y < 0 || Y >= IMG_H || X < 0 || X >= IMG_W) {
                                v = 0.0f;
                            } else {
                                v = g0 * sm.u.hbuf[c][r][s];
                                v = fmaf(g1, sm.u.hbuf[c][r + 1][s], v);
                                v = fmaf(g2, sm.u.hbuf[c][r + 2][s], v);
                                v = fmaf(g3, sm.u.hbuf[c][r + 3][s], v);
                                v = fmaf(g4, sm.u.hbuf[c][r + 4][s], v);
                            }
                        } else {
                            v = g0 * sm.u.hbuf[c][r][s];
                            v = fmaf(g1, sm.u.hbuf[c][r + 1][s], v);
                            v = fmaf(g2, sm.u.hbuf[c][r + 2][s], v);
                            v = fmaf(g3, sm.u.hbuf[c][r + 3][s], v);
                            v = fmaf(g4, sm.u.hbuf[c][r + 4][s], v);
                        }
                        sm.sblur[c][r][s] = v;
                        if (central) {
                            blurred_out[c * HW + (by0 + r - 2) * IMG_W + (bx0 + s - 2)] = v;
                        }
                    }
                }
            }
        }
    }
    __syncthreads();   // sblur ready; hbuf dead -> smag/sk may use its storage

    // ---- Stage B: mag over 34x34; orientation for central 32x32 ----
#pragma unroll
    for (int j = 0; j < 5; j++) {
        const int r = ty + 8 * j;               // need r < 34
        if (j < 4 || ty < 2) {
#pragma unroll
            for (int grp = 0; grp < 2; grp++) {
                const int s = grp ? (32 + tx) : tx;
                if (grp == 0 || tx < 2) {
                    float m = 0.0f, sgx = 0.0f, sgy = 0.0f;
                    bool ok = true;
                    if (BORDER) {
                        const int Y = by0 - 1 + r, X = bx0 - 1 + s;
                        ok = (Y >= 0 && Y < IMG_H && X >= 0 && X < IMG_W);
                    }
                    if (ok) {
#pragma unroll
                        for (int c = 0; c < 3; c++) {
                            const float a  = sm.sblur[c][r][s];
                            const float b  = sm.sblur[c][r][s + 1];
                            const float cc = sm.sblur[c][r][s + 2];
                            const float d  = sm.sblur[c][r + 1][s];
                            const float e  = sm.sblur[c][r + 1][s + 2];
                            const float f  = sm.sblur[c][r + 2][s];
                            const float g  = sm.sblur[c][r + 2][s + 1];
                            const float h  = sm.sblur[c][r + 2][s + 2];
                            const float gx = (a - cc) + 2.0f * (d - e) + (f - h);
                            const float gy = (a + 2.0f * b + cc) - (f + 2.0f * g + h);
                            m += sqrt_approx(fmaf(gx, gx, gy * gy));
                            sgx += gx;
                            sgy += gy;
                        }
                    }
                    sm.u.b.smag[r][s] = m;

                    // orientation only for central pixels
                    if (r >= 1 && r < 33 && s >= 1 && s < 33) {
                        const float ax = fabsf(sgx), ay = fabsf(sgy);
                        const bool gxneg = sgx < 0.0f;
                        const bool gypos = (__float_as_int(sgy) >= 0);
                        int kq;
                        bool risky;
                        if (!gxneg) {
                            const float lo = T1_POS * ax, hi = T2_POS * ax;
                            risky = (fabsf(ay - lo) <= BAND1 * ax) ||
                                    (fabsf(ay - hi) <= BAND2 * ax);
                            if (ay < lo)      kq = 4;
                            else if (ay < hi) kq = gypos ? 5 : 3;
                            else              kq = gypos ? 6 : 2;
                        } else {
                            const float lo = T1_NEG * ax, hi = T2_NEG * ax;
                            risky = (fabsf(ay - lo) <= BAND1 * ax) ||
                                    (fabsf(ay - hi) <= BAND2 * ax) ||
                                    (ay <= 1e-3f * ax);
                            if (ay < lo)      kq = gypos ? 8 : 0;
                            else if (ay < hi) kq = gypos ? 7 : 1;
                            else              kq = gypos ? 6 : 2;
                        }
                        if (risky) {
                            kq = orient_k_exact_smem(sm.sblur, r - 1, s - 1);
                        }
                        sm.u.b.sk[r - 1][s - 1] = (signed char)kq;
                    }
                }
            }
        }
    }
    __syncthreads();

    // ---- Stage C: NMS + write mag/orient/early/thin/thresh ----
#pragma unroll
    for (int k = 0; k < 4; k++) {
        const int y = ty + 8 * k;
        const int Y = by0 + y, X = bx0 + tx;

        const float m = sm.u.b.smag[y + 1][tx + 1];
        const int kq  = (int)sm.u.b.sk[y][tx];

        const int idx = Y * IMG_W + X;
        mag_out[idx]    = m;
        orient_out[idx] = 45.0f * (float)kq;
        early_out[idx]  = (m < THRESH) ? 0.0f : m;

        const int ip  = kq & 7;
        const int in_ = (kq + 4) & 7;
        const int pdy = unpack_d(DY_PACK, ip),  pdx = unpack_d(DX_PACK, ip);
        const int ndy = unpack_d(DY_PACK, in_), ndx = unpack_d(DX_PACK, in_);

        const float npos = sm.u.b.smag[y + 1 + pdy][tx + 1 + pdx];
        const float nneg = sm.u.b.smag[y + 1 + ndy][tx + 1 + ndx];
        const float sel_min = fminf(m - npos, m - nneg);

        bool is_max;
        const float eps = 4e-6f * fmaxf(m, 1.0f);
        if (fabsf(sel_min) > eps) {
            is_max = sel_min > 0.0f;
        } else {
            const double md = mag_exact_smem(sm.sblur, y, tx, Y, X);
            const double dp = md - mag_exact_smem(sm.sblur, y + pdy, tx + pdx, Y + pdy, X + pdx);
            const double dn = md - mag_exact_smem(sm.sblur, y + ndy, tx + ndx, Y + ndy, X + ndx);
            is_max = fmin(dp, dn) > 0.0;
        }

        const float thin = is_max ? m : 0.0f;
        thin_out[idx]   = thin;
        thresh_out[idx] = (thin < THRESH) ? 0.0f : thin;
    }
}

__global__ void __launch_bounds__(256, 6)
canny_fused(const float* __restrict__ img,
            const float* __restrict__ g5,
            float* __restrict__ blurred_out,
            float* __restrict__ mag_out,
            float* __restrict__ orient_out,
            float* __restrict__ early_out,
            float* __restrict__ thin_out,
            float* __restrict__ thresh_out) {
    __shared__ Smem sm;

    const int tx  = threadIdx.x;
    const int ty  = threadIdx.y;
    const int bx0 = blockIdx.x * 32;
    const int by0 = blockIdx.y * 32;

    const float g0 = __ldg(g5 + 0), g1 = __ldg(g5 + 1), g2 = __ldg(g5 + 2),
                g3 = __ldg(g5 + 3), g4 = __ldg(g5 + 4);

    const bool interior = (bx0 != 0) && (bx0 != IMG_W - 32) &&
                          (by0 != 0) && (by0 != IMG_H - 32);
    if (interior) {
        canny_body<false>(sm, img, g0, g1, g2, g3, g4, bx0, by0, tx, ty,
                          blurred_out, mag_out, orient_out, early_out,
                          thin_out, thresh_out);
    } else {
        canny_body<true>(sm, img, g0, g1, g2, g3, g4, bx0, by0, tx, ty,
                         blurred_out, mag_out, orient_out, early_out,
                         thin_out, thresh_out);
    }
}

// ---------------------------------------------------------------------------
// Output layout (concatenated reference tuple, fp32):
//   [0,3HW) blurred | [3HW,4HW) mag | [4HW,5HW) orient | [5HW,6HW) thin
//   [6HW,7HW) thresholded | [7HW,8HW) early
// ---------------------------------------------------------------------------
extern "C" void kernel_launch(void* const* d_in, const int* in_sizes, int n_in,
                              void* d_out, int out_size) {
    const float* img  = (const float*)d_in[0];
    const float* gh_w = (const float*)d_in[1];

    float* out      = (float*)d_out;
    float* blurred  = out;
    float* mag      = out + 3 * (size_t)HW;
    float* orient   = out + 4 * (size_t)HW;
    float* thin     = out + 5 * (size_t)HW;
    float* threshed = out + 6 * (size_t)HW;
    float* early    = out + 7 * (size_t)HW;

    dim3 block(32, 8, 1);
    dim3 grid(IMG_W / 32, IMG_H / 32, 1);
    canny_fused<<<grid, block>>>(img, gh_w, blurred, mag, orient, early,
                                 thin, threshed);
}

// round 8
// speedup vs baseline: 1.4332x; 1.1166x over previous
#include <cuda_runtime.h>
#include <math.h>

#define IMG_H 2048
#define IMG_W 2048
#define HW (IMG_H * IMG_W)
#define THRESH 10.0f

// 180 / 3.14159 (reference constant, NOT pi)
#define RAD2DEG_D 57.29582790879777437539

// Octant boundary tangents (see R7 derivation)
#define T1_POS 0.41421317376f
#define T2_POS 2.41420677f
#define T1_NEG 0.41421628f
#define T2_NEG 2.41422489f
#define BAND1 1.0e-3f
#define BAND2 6.0e-3f

// Layouts (all +offset cols so float4 accesses are 16B aligned):
//   hbuf[c][r][j+2]   : h-sum at image (by0-4+r, bx0-4+j), j in 2..37 (cols 4..39)
//   sblur[c][r][s+4]  : blurred at image (by0-2+r, bx0-2+s), s in 0..35 (cols 4..39)
//   smag[r][s+4]      : grad mag at image (by0-1+r, bx0-1+s), s in 0..33
//   sk[y][x]          : quantized orientation k for central pixel (y,x)
struct Smem {
    union {
        float hbuf[3][40][40];
        struct {
            float smag[34][44];
            signed char sk[32][32];
        } b;
    } u;
    float sblur[3][36][44];
};

__device__ __forceinline__ float ldz_g(const float* __restrict__ p, int Y, int X) {
    return (Y >= 0 && Y < IMG_H && X >= 0 && X < IMG_W) ? __ldg(p + Y * IMG_W + X) : 0.0f;
}

__device__ __forceinline__ float sqrt_approx(float x) {
    float r;
    asm("sqrt.approx.f32 %0, %1;" : "=f"(r) : "f"(x));
    return r;
}

// ---------------------------------------------------------------------------
// Exact (fp64) helpers on the smem blurred tile. (y,x) are central coords:
// image (by0+y, bx0+x) = sblur[c][y+2][x+6].
// ---------------------------------------------------------------------------
__device__ __noinline__ void sobel_exact_smem(const float (*sb)[36][44],
                                              int y, int x,
                                              double& ogx, double& ogy, double& omag) {
    double gxs = 0.0, gys = 0.0, mg = 0.0;
#pragma unroll
    for (int c = 0; c < 3; c++) {
        const double a  = sb[c][y + 1][x + 5];
        const double b  = sb[c][y + 1][x + 6];
        const double cc = sb[c][y + 1][x + 7];
        const double d  = sb[c][y + 2][x + 5];
        const double e  = sb[c][y + 2][x + 7];
        const double f  = sb[c][y + 3][x + 5];
        const double g  = sb[c][y + 3][x + 6];
        const double h  = sb[c][y + 3][x + 7];
        const double gx = (a - cc) + 2.0 * (d - e) + (f - h);
        const double gy = (a + 2.0 * b + cc) - (f + 2.0 * g + h);
        gxs += gx; gys += gy;
        mg += sqrt(gx * gx + gy * gy);
    }
    ogx = gxs; ogy = gys; omag = mg;
}

__device__ __noinline__ int orient_k_exact_smem(const float (*sb)[36][44],
                                                int y, int x) {
    double gx, gy, m;
    sobel_exact_smem(sb, y, x, gx, gy, m);
    const double orient = atan2(gy, gx) * RAD2DEG_D + 180.0;
    return (int)rint(orient / 45.0);
}

__device__ __noinline__ double mag_exact_smem(const float (*sb)[36][44],
                                              int y, int x, int Y, int X) {
    if (X < 0 || X >= IMG_W || Y < 0 || Y >= IMG_H) return 0.0;
    double gx, gy, m;
    sobel_exact_smem(sb, y, x, gx, gy, m);
    return m;
}

// Packed direction tables (value+1 in nibbles, dir d at nibble 4d)
#define DX_PACK 0x21000122u
#define DY_PACK 0x00012221u
__device__ __forceinline__ int unpack_d(unsigned pack, int d) {
    return (int)((pack >> (4 * d)) & 0xFu) - 1;
}

// Quantized-octant computation with risk detection (same as R7).
__device__ __forceinline__ int orient_k_fast(Smem& sm, float sgx, float sgy,
                                             int cy, int cx) {
    const float ax = fabsf(sgx), ay = fabsf(sgy);
    const bool gxneg = sgx < 0.0f;
    const bool gypos = (__float_as_int(sgy) >= 0);
    int kq;
    bool risky;
    if (!gxneg) {
        const float lo = T1_POS * ax, hi = T2_POS * ax;
        risky = (fabsf(ay - lo) <= BAND1 * ax) || (fabsf(ay - hi) <= BAND2 * ax);
        if (ay < lo)      kq = 4;
        else if (ay < hi) kq = gypos ? 5 : 3;
        else              kq = gypos ? 6 : 2;
    } else {
        const float lo = T1_NEG * ax, hi = T2_NEG * ax;
        risky = (fabsf(ay - lo) <= BAND1 * ax) || (fabsf(ay - hi) <= BAND2 * ax) ||
                (ay <= 1e-3f * ax);
        if (ay < lo)      kq = gypos ? 8 : 0;
        else if (ay < hi) kq = gypos ? 7 : 1;
        else              kq = gypos ? 6 : 2;
    }
    if (risky) kq = orient_k_exact_smem(sm.sblur, cy, cx);
    return kq;
}

// ---------------------------------------------------------------------------
// Interior fast path (vectorized)
// ---------------------------------------------------------------------------
__device__ __forceinline__ void body_interior(
    Smem& sm, const float* __restrict__ img,
    float g0, float g1, float g2, float g3, float g4,
    int bx0, int by0, int tid) {

    // ---- A1: horizontal blur. 1080 tasks = 3ch x 40 rows x 9 groups ----
    for (int t = tid; t < 1080; t += 256) {
        const int c = t / 360, rem = t - c * 360;
        const int r = rem / 9, g = rem - r * 9;
        const int Y = by0 - 4 + r;
        const float* row = img + c * HW + Y * IMG_W + (bx0 + 4 * g - 4);
        const float4 A = __ldg((const float4*)row);
        const float4 B = __ldg((const float4*)(row + 4));
        const float w[8] = {A.x, A.y, A.z, A.w, B.x, B.y, B.z, B.w};
        float o[4];
#pragma unroll
        for (int i = 0; i < 4; i++) {
            float v = g2 * w[i + 2];
            v = fmaf(g0, w[i],     v);
            v = fmaf(g1, w[i + 1], v);
            v = fmaf(g3, w[i + 3], v);
            v = fmaf(g4, w[i + 4], v);
            o[i] = v;
        }
        *(float4*)&sm.u.hbuf[c][r][4 * g + 4] = make_float4(o[0], o[1], o[2], o[3]);
    }
    __syncthreads();

    // ---- A2: vertical blur. 972 tasks = 3ch x 36 rows x 9 groups ----
    for (int t = tid; t < 972; t += 256) {
        const int c = t / 324, rem = t - c * 324;
        const int r = rem / 9, g = rem - r * 9;
        const int col = 4 * g + 4;
        const float4 h0 = *(const float4*)&sm.u.hbuf[c][r][col];
        const float4 h1 = *(const float4*)&sm.u.hbuf[c][r + 1][col];
        const float4 h2 = *(const float4*)&sm.u.hbuf[c][r + 2][col];
        const float4 h3 = *(const float4*)&sm.u.hbuf[c][r + 3][col];
        const float4 h4 = *(const float4*)&sm.u.hbuf[c][r + 4][col];
        float4 o;
        o.x = fmaf(g4, h4.x, fmaf(g3, h3.x, fmaf(g2, h2.x, fmaf(g1, h1.x, g0 * h0.x))));
        o.y = fmaf(g4, h4.y, fmaf(g3, h3.y, fmaf(g2, h2.y, fmaf(g1, h1.y, g0 * h0.y))));
        o.z = fmaf(g4, h4.z, fmaf(g3, h3.z, fmaf(g2, h2.z, fmaf(g1, h1.z, g0 * h0.z))));
        o.w = fmaf(g4, h4.w, fmaf(g3, h3.w, fmaf(g2, h2.w, fmaf(g1, h1.w, g0 * h0.w))));
        *(float4*)&sm.sblur[c][r][col] = o;
    }
    __syncthreads();
}

// ---------------------------------------------------------------------------
// Border slow path (scalar, zero-padded)
// ---------------------------------------------------------------------------
__device__ __forceinline__ void body_border(
    Smem& sm, const float* __restrict__ img,
    float g0, float g1, float g2, float g3, float g4,
    int bx0, int by0, int tid) {

    // A1 scalar: 4320 tasks = 3 x 40 x 36 (j = 2..37)
    for (int t = tid; t < 4320; t += 256) {
        const int c = t / 1440, rem = t - c * 1440;
        const int r = rem / 36, j = rem - r * 36 + 2;
        const int Y = by0 - 4 + r;
        const int X = bx0 - 4 + j;
        const float* src = img + c * HW;
        float v = g2 * ldz_g(src, Y, X);
        v = fmaf(g0, ldz_g(src, Y, X - 2), v);
        v = fmaf(g1, ldz_g(src, Y, X - 1), v);
        v = fmaf(g3, ldz_g(src, Y, X + 1), v);
        v = fmaf(g4, ldz_g(src, Y, X + 2), v);
        sm.u.hbuf[c][r][j + 2] = v;
    }
    __syncthreads();

    // A2 scalar: 3888 tasks = 3 x 36 x 36; zero outside image
    for (int t = tid; t < 3888; t += 256) {
        const int c = t / 1296, rem = t - c * 1296;
        const int r = rem / 36, s = rem - r * 36;
        const int Y = by0 - 2 + r, X = bx0 - 2 + s;
        float v = 0.0f;
        if (Y >= 0 && Y < IMG_H && X >= 0 && X < IMG_W) {
            v = g0 * sm.u.hbuf[c][r][s + 4];
            v = fmaf(g1, sm.u.hbuf[c][r + 1][s + 4], v);
            v = fmaf(g2, sm.u.hbuf[c][r + 2][s + 4], v);
            v = fmaf(g3, sm.u.hbuf[c][r + 3][s + 4], v);
            v = fmaf(g4, sm.u.hbuf[c][r + 4][s + 4], v);
        }
        sm.sblur[c][r][s + 4] = v;
    }
    __syncthreads();
}

template <bool BORDER>
__device__ __forceinline__ void canny_tail(
    Smem& sm, int bx0, int by0, int tid,
    float* __restrict__ blurred_out, float* __restrict__ mag_out,
    float* __restrict__ orient_out, float* __restrict__ early_out,
    float* __restrict__ thin_out, float* __restrict__ thresh_out) {

    // ---- blurred output: vector STG (no barrier needed; reads post-A2-sync) ----
    {
        const int r = tid >> 3, g = tid & 7;
#pragma unroll
        for (int c = 0; c < 3; c++) {
            float4 o;
            o.x = sm.sblur[c][r + 2][4 * g + 6];
            o.y = sm.sblur[c][r + 2][4 * g + 7];
            o.z = sm.sblur[c][r + 2][4 * g + 8];
            o.w = sm.sblur[c][r + 2][4 * g + 9];
            *(float4*)&blurred_out[c * HW + (by0 + r) * IMG_W + bx0 + 4 * g] = o;
        }
    }

    // ---- Stage B: mag (+orientation for central px) ----
    if (!BORDER) {
        // 306 tasks = 34 rows x 9 groups, vectorized
        for (int t = tid; t < 306; t += 256) {
            const int r = t / 9, g = t - 9 * r;
            const int col = 4 * g + 4;
            float m[4]  = {0.f, 0.f, 0.f, 0.f};
            float sx[4] = {0.f, 0.f, 0.f, 0.f};
            float sy[4] = {0.f, 0.f, 0.f, 0.f};
#pragma unroll
            for (int c = 0; c < 3; c++) {
                const float4 L0 = *(const float4*)&sm.sblur[c][r][col];
                const float4 R0 = *(const float4*)&sm.sblur[c][r][col + 4];
                const float4 L1 = *(const float4*)&sm.sblur[c][r + 1][col];
                const float4 R1 = *(const float4*)&sm.sblur[c][r + 1][col + 4];
                const float4 L2 = *(const float4*)&sm.sblur[c][r + 2][col];
                const float4 R2 = *(const float4*)&sm.sblur[c][r + 2][col + 4];
                const float w0[6] = {L0.x, L0.y, L0.z, L0.w, R0.x, R0.y};
                const float w1[6] = {L1.x, L1.y, L1.z, L1.w, R1.x, R1.y};
                const float w2[6] = {L2.x, L2.y, L2.z, L2.w, R2.x, R2.y};
#pragma unroll
                for (int i = 0; i < 4; i++) {
                    const float a  = w0[i], b = w0[i + 1], cc = w0[i + 2];
                    const float d  = w1[i], e = w1[i + 2];
                    const float f  = w2[i], gg = w2[i + 1], h = w2[i + 2];
                    const float gx = (a - cc) + 2.0f * (d - e) + (f - h);
                    const float gy = (a + 2.0f * b + cc) - (f + 2.0f * gg + h);
                    m[i] += sqrt_approx(fmaf(gx, gx, gy * gy));
                    sx[i] += gx;
                    sy[i] += gy;
                }
            }
            *(float4*)&sm.u.b.smag[r][col] = make_float4(m[0], m[1], m[2], m[3]);
#pragma unroll
            for (int i = 0; i < 4; i++) {
                const int s = 4 * g + i;
                if (r >= 1 && r < 33 && s >= 1 && s < 33) {
                    sm.u.b.sk[r - 1][s - 1] =
                        (signed char)orient_k_fast(sm, sx[i], sy[i], r - 1, s - 1);
                }
            }
        }
    } else {
        // scalar: 1156 tasks = 34 x 34
        for (int t = tid; t < 1156; t += 256) {
            const int r = t / 34, s = t - 34 * r;
            const int Y = by0 - 1 + r, X = bx0 - 1 + s;
            float m = 0.0f, sgx = 0.0f, sgy = 0.0f;
            if (Y >= 0 && Y < IMG_H && X >= 0 && X < IMG_W) {
#pragma unroll
                for (int c = 0; c < 3; c++) {
                    const float a  = sm.sblur[c][r][s + 4];
                    const float b  = sm.sblur[c][r][s + 5];
                    const float cc = sm.sblur[c][r][s + 6];
                    const float d  = sm.sblur[c][r + 1][s + 4];
                    const float e  = sm.sblur[c][r + 1][s + 6];
                    const float f  = sm.sblur[c][r + 2][s + 4];
                    const float gg = sm.sblur[c][r + 2][s + 5];
                    const float h  = sm.sblur[c][r + 2][s + 6];
                    const float gx = (a - cc) + 2.0f * (d - e) + (f - h);
                    const float gy = (a + 2.0f * b + cc) - (f + 2.0f * gg + h);
                    m += sqrt_approx(fmaf(gx, gx, gy * gy));
                    sgx += gx;
                    sgy += gy;
                }
            }
            sm.u.b.smag[r][s + 4] = m;
            if (r >= 1 && r < 33 && s >= 1 && s < 33) {
                sm.u.b.sk[r - 1][s - 1] =
                    (signed char)orient_k_fast(sm, sgx, sgy, r - 1, s - 1);
            }
        }
    }
    __syncthreads();

    // ---- Stage C: NMS + 5 vector output stores. 256 tasks exactly. ----
    {
        const int y = tid >> 3, g = tid & 7;
        const int Y = by0 + y;
        const int Xb = bx0 + 4 * g;
        float vm[4], vo[4], ve[4], vt[4], vh[4];
#pragma unroll
        for (int i = 0; i < 4; i++) {
            const int x = 4 * g + i;
            const float m = sm.u.b.smag[y + 1][x + 5];
            const int kq  = (int)sm.u.b.sk[y][x];

            vm[i] = m;
            vo[i] = 45.0f * (float)kq;
            ve[i] = (m < THRESH) ? 0.0f : m;

            const int ip  = kq & 7;
            const int in_ = (kq + 4) & 7;
            const int pdy = unpack_d(DY_PACK, ip),  pdx = unpack_d(DX_PACK, ip);
            const int ndy = unpack_d(DY_PACK, in_), ndx = unpack_d(DX_PACK, in_);

            const float npos = sm.u.b.smag[y + 1 + pdy][x + 5 + pdx];
            const float nneg = sm.u.b.smag[y + 1 + ndy][x + 5 + ndx];
            const float sel_min = fminf(m - npos, m - nneg);

            bool is_max;
            const float eps = 4e-6f * fmaxf(m, 1.0f);
            if (fabsf(sel_min) > eps) {
                is_max = sel_min > 0.0f;
            } else {
                const double md = mag_exact_smem(sm.sblur, y, x, Y, Xb + i);
                const double dp = md - mag_exact_smem(sm.sblur, y + pdy, x + pdx,
                                                      Y + pdy, Xb + i + pdx);
                const double dn = md - mag_exact_smem(sm.sblur, y + ndy, x + ndx,
                                                      Y + ndy, Xb + i + ndx);
                is_max = fmin(dp, dn) > 0.0;
            }

            const float thin = is_max ? m : 0.0f;
            vt[i] = thin;
            vh[i] = (thin < THRESH) ? 0.0f : thin;
        }
        const int idx = Y * IMG_W + Xb;
        *(float4*)&mag_out[idx]    = make_float4(vm[0], vm[1], vm[2], vm[3]);
        *(float4*)&orient_out[idx] = make_float4(vo[0], vo[1], vo[2], vo[3]);
        *(float4*)&early_out[idx]  = make_float4(ve[0], ve[1], ve[2], ve[3]);
        *(float4*)&thin_out[idx]   = make_float4(vt[0], vt[1], vt[2], vt[3]);
        *(float4*)&thresh_out[idx] = make_float4(vh[0], vh[1], vh[2], vh[3]);
    }
}

__global__ void __launch_bounds__(256, 5)
canny_fused(const float* __restrict__ img,
            const float* __restrict__ g5,
            float* __restrict__ blurred_out,
            float* __restrict__ mag_out,
            float* __restrict__ orient_out,
            float* __restrict__ early_out,
            float* __restrict__ thin_out,
            float* __restrict__ thresh_out) {
    __shared__ Smem sm;

    const int tid = threadIdx.x;
    const int bx0 = blockIdx.x * 32;
    const int by0 = blockIdx.y * 32;

    const float g0 = __ldg(g5 + 0), g1 = __ldg(g5 + 1), g2 = __ldg(g5 + 2),
                g3 = __ldg(g5 + 3), g4 = __ldg(g5 + 4);

    const bool interior = (bx0 != 0) && (bx0 != IMG_W - 32) &&
                          (by0 != 0) && (by0 != IMG_H - 32);
    if (interior) {
        body_interior(sm, img, g0, g1, g2, g3, g4, bx0, by0, tid);
        canny_tail<false>(sm, bx0, by0, tid, blurred_out, mag_out, orient_out,
                          early_out, thin_out, thresh_out);
    } else {
        body_border(sm, img, g0, g1, g2, g3, g4, bx0, by0, tid);
        canny_tail<true>(sm, bx0, by0, tid, blurred_out, mag_out, orient_out,
                         early_out, thin_out, thresh_out);
    }
}

// ---------------------------------------------------------------------------
// Output layout (concatenated reference tuple, fp32):
//   [0,3HW) blurred | [3HW,4HW) mag | [4HW,5HW) orient | [5HW,6HW) thin
//   [6HW,7HW) thresholded | [7HW,8HW) early
// ---------------------------------------------------------------------------
extern "C" void kernel_launch(void* const* d_in, const int* in_sizes, int n_in,
                              void* d_out, int out_size) {
    const float* img  = (const float*)d_in[0];
    const float* gh_w = (const float*)d_in[1];

    float* out      = (float*)d_out;
    float* blurred  = out;
    float* mag      = out + 3 * (size_t)HW;
    float* orient   = out + 4 * (size_t)HW;
    float* thin     = out + 5 * (size_t)HW;
    float* threshed = out + 6 * (size_t)HW;
    float* early    = out + 7 * (size_t)HW;

    dim3 block(256, 1, 1);
    dim3 grid(IMG_W / 32, IMG_H / 32, 1);
    canny_fused<<<grid, block>>>(img, gh_w, blurred, mag, orient, early,
                                 thin, threshed);
}

// round 9
// speedup vs baseline: 1.5163x; 1.0580x over previous
#include <cuda_runtime.h>
#include <math.h>

#define IMG_H 2048
#define IMG_W 2048
#define HW (IMG_H * IMG_W)
#define THRESH 10.0f

// 180 / 3.14159 (reference constant, NOT pi)
#define RAD2DEG_D 57.29582790879777437539

// Octant boundary tangents (see R7 derivation)
#define T1_POS 0.41421317376f
#define T2_POS 2.41420677f
#define T1_NEG 0.41421628f
#define T2_NEG 2.41422489f
#define BAND1 1.0e-3f
#define BAND2 6.0e-3f

// Layouts:
//   hbuf[c][r][s]    : h-sum at image (by0-4+r, bx0-2+s), s in 0..35
//   sblur[c][r][s+4] : blurred at image (by0-2+r, bx0-2+s), s in 0..35 (cols 4..39)
//   smag[r][s+4]     : grad mag at image (by0-1+r, bx0-1+s), s in 0..33
//   sk[y][x]         : quantized orientation for central pixel (y,x)
struct Smem {
    union {
        float hbuf[3][40][36];
        struct {
            float smag[34][44];
            signed char sk[32][32];
        } b;
    } u;
    float sblur[3][36][44];
};

__device__ __forceinline__ float ldz_g(const float* __restrict__ p, int Y, int X) {
    return (Y >= 0 && Y < IMG_H && X >= 0 && X < IMG_W) ? __ldg(p + Y * IMG_W + X) : 0.0f;
}

__device__ __forceinline__ float sqrt_approx(float x) {
    float r;
    asm("sqrt.approx.f32 %0, %1;" : "=f"(r) : "f"(x));
    return r;
}

// ---------------------------------------------------------------------------
// Exact (fp64) helpers on the smem blurred tile. (y,x) central coords:
// image (by0+y, bx0+x) = sblur[c][y+2][x+6].
// ---------------------------------------------------------------------------
__device__ __noinline__ void sobel_exact_smem(const float (*sb)[36][44],
                                              int y, int x,
                                              double& ogx, double& ogy, double& omag) {
    double gxs = 0.0, gys = 0.0, mg = 0.0;
#pragma unroll
    for (int c = 0; c < 3; c++) {
        const double a  = sb[c][y + 1][x + 5];
        const double b  = sb[c][y + 1][x + 6];
        const double cc = sb[c][y + 1][x + 7];
        const double d  = sb[c][y + 2][x + 5];
        const double e  = sb[c][y + 2][x + 7];
        const double f  = sb[c][y + 3][x + 5];
        const double g  = sb[c][y + 3][x + 6];
        const double h  = sb[c][y + 3][x + 7];
        const double gx = (a - cc) + 2.0 * (d - e) + (f - h);
        const double gy = (a + 2.0 * b + cc) - (f + 2.0 * g + h);
        gxs += gx; gys += gy;
        mg += sqrt(gx * gx + gy * gy);
    }
    ogx = gxs; ogy = gys; omag = mg;
}

__device__ __noinline__ int orient_k_exact_smem(const float (*sb)[36][44],
                                                int y, int x) {
    double gx, gy, m;
    sobel_exact_smem(sb, y, x, gx, gy, m);
    const double orient = atan2(gy, gx) * RAD2DEG_D + 180.0;
    return (int)rint(orient / 45.0);
}

__device__ __noinline__ double mag_exact_smem(const float (*sb)[36][44],
                                              int y, int x, int Y, int X) {
    if (X < 0 || X >= IMG_W || Y < 0 || Y >= IMG_H) return 0.0;
    double gx, gy, m;
    sobel_exact_smem(sb, y, x, gx, gy, m);
    return m;
}

// Packed direction tables (value+1 in nibbles, dir d at nibble 4d)
#define DX_PACK 0x21000122u
#define DY_PACK 0x00012221u
__device__ __forceinline__ int unpack_d(unsigned pack, int d) {
    return (int)((pack >> (4 * d)) & 0xFu) - 1;
}

__device__ __forceinline__ int orient_k_fast(Smem& sm, float sgx, float sgy,
                                             int cy, int cx) {
    const float ax = fabsf(sgx), ay = fabsf(sgy);
    const bool gxneg = sgx < 0.0f;
    const bool gypos = (__float_as_int(sgy) >= 0);
    int kq;
    bool risky;
    if (!gxneg) {
        const float lo = T1_POS * ax, hi = T2_POS * ax;
        risky = (fabsf(ay - lo) <= BAND1 * ax) || (fabsf(ay - hi) <= BAND2 * ax);
        if (ay < lo)      kq = 4;
        else if (ay < hi) kq = gypos ? 5 : 3;
        else              kq = gypos ? 6 : 2;
    } else {
        const float lo = T1_NEG * ax, hi = T2_NEG * ax;
        risky = (fabsf(ay - lo) <= BAND1 * ax) || (fabsf(ay - hi) <= BAND2 * ax) ||
                (ay <= 1e-3f * ax);
        if (ay < lo)      kq = gypos ? 8 : 0;
        else if (ay < hi) kq = gypos ? 7 : 1;
        else              kq = gypos ? 6 : 2;
    }
    if (risky) kq = orient_k_exact_smem(sm.sblur, cy, cx);
    return kq;
}

// ---------------------------------------------------------------------------
// Per-task bodies (interior fast path)
// ---------------------------------------------------------------------------
__device__ __forceinline__ void a1_task(Smem& sm, const float* __restrict__ img,
                                        float g0, float g1, float g2, float g3,
                                        float g4, int bx0, int by0, int t) {
    const int c = t / 360, rem = t - c * 360;
    const int r = rem / 9, g = rem - r * 9;
    const float* row = img + c * HW + (by0 - 4 + r) * IMG_W + (bx0 + 4 * g - 4);
    const float4 A = __ldg((const float4*)row);
    const float4 B = __ldg((const float4*)(row + 4));
    const float w[8] = {A.x, A.y, A.z, A.w, B.x, B.y, B.z, B.w};
    float o[4];
#pragma unroll
    for (int i = 0; i < 4; i++) {
        float v = g2 * w[i + 2];
        v = fmaf(g0, w[i],     v);
        v = fmaf(g1, w[i + 1], v);
        v = fmaf(g3, w[i + 3], v);
        v = fmaf(g4, w[i + 4], v);
        o[i] = v;
    }
    *(float4*)&sm.u.hbuf[c][r][4 * g] = make_float4(o[0], o[1], o[2], o[3]);
}

__device__ __forceinline__ void a2_task(Smem& sm, float g0, float g1, float g2,
                                        float g3, float g4, int t) {
    const int c = t / 324, rem = t - c * 324;
    const int r = rem / 9, g = rem - r * 9;
    const int ch = 4 * g;              // hbuf col
    const float4 h0 = *(const float4*)&sm.u.hbuf[c][r][ch];
    const float4 h1 = *(const float4*)&sm.u.hbuf[c][r + 1][ch];
    const float4 h2 = *(const float4*)&sm.u.hbuf[c][r + 2][ch];
    const float4 h3 = *(const float4*)&sm.u.hbuf[c][r + 3][ch];
    const float4 h4 = *(const float4*)&sm.u.hbuf[c][r + 4][ch];
    float4 o;
    o.x = fmaf(g4, h4.x, fmaf(g3, h3.x, fmaf(g2, h2.x, fmaf(g1, h1.x, g0 * h0.x))));
    o.y = fmaf(g4, h4.y, fmaf(g3, h3.y, fmaf(g2, h2.y, fmaf(g1, h1.y, g0 * h0.y))));
    o.z = fmaf(g4, h4.z, fmaf(g3, h3.z, fmaf(g2, h2.z, fmaf(g1, h1.z, g0 * h0.z))));
    o.w = fmaf(g4, h4.w, fmaf(g3, h3.w, fmaf(g2, h2.w, fmaf(g1, h1.w, g0 * h0.w))));
    *(float4*)&sm.sblur[c][r][4 * g + 4] = o;
}

__device__ __forceinline__ void b_task(Smem& sm, int t) {
    const int r = t / 9, g = t - 9 * r;
    const int col = 4 * g + 4;
    float m[4]  = {0.f, 0.f, 0.f, 0.f};
    float sx[4] = {0.f, 0.f, 0.f, 0.f};
    float sy[4] = {0.f, 0.f, 0.f, 0.f};
#pragma unroll
    for (int c = 0; c < 3; c++) {
        const float4 L0 = *(const float4*)&sm.sblur[c][r][col];
        const float4 R0 = *(const float4*)&sm.sblur[c][r][col + 4];
        const float4 L1 = *(const float4*)&sm.sblur[c][r + 1][col];
        const float4 R1 = *(const float4*)&sm.sblur[c][r + 1][col + 4];
        const float4 L2 = *(const float4*)&sm.sblur[c][r + 2][col];
        const float4 R2 = *(const float4*)&sm.sblur[c][r + 2][col + 4];
        const float w0[6] = {L0.x, L0.y, L0.z, L0.w, R0.x, R0.y};
        const float w1[6] = {L1.x, L1.y, L1.z, L1.w, R1.x, R1.y};
        const float w2[6] = {L2.x, L2.y, L2.z, L2.w, R2.x, R2.y};
#pragma unroll
        for (int i = 0; i < 4; i++) {
            const float a  = w0[i], b = w0[i + 1], cc = w0[i + 2];
            const float d  = w1[i], e = w1[i + 2];
            const float f  = w2[i], gg = w2[i + 1], h = w2[i + 2];
            const float gx = (a - cc) + 2.0f * (d - e) + (f - h);
            const float gy = (a + 2.0f * b + cc) - (f + 2.0f * gg + h);
            m[i] += sqrt_approx(fmaf(gx, gx, gy * gy));
            sx[i] += gx;
            sy[i] += gy;
        }
    }
    *(float4*)&sm.u.b.smag[r][col] = make_float4(m[0], m[1], m[2], m[3]);
#pragma unroll
    for (int i = 0; i < 4; i++) {
        const int s = 4 * g + i;
        if (r >= 1 && r < 33 && s >= 1 && s < 33) {
            sm.u.b.sk[r - 1][s - 1] =
                (signed char)orient_k_fast(sm, sx[i], sy[i], r - 1, s - 1);
        }
    }
}

// ---------------------------------------------------------------------------
// Border slow path (scalar, zero-padded)
// ---------------------------------------------------------------------------
__device__ __forceinline__ void body_border(
    Smem& sm, const float* __restrict__ img,
    float g0, float g1, float g2, float g3, float g4,
    int bx0, int by0, int tid) {

    // A1 scalar: 4320 tasks = 3 x 40 x 36 (hbuf col s, X = bx0-2+s)
    for (int t = tid; t < 4320; t += 256) {
        const int c = t / 1440, rem = t - c * 1440;
        const int r = rem / 36, s = rem - r * 36;
        const int Y = by0 - 4 + r;
        const int X = bx0 - 2 + s;
        const float* src = img + c * HW;
        float v = g2 * ldz_g(src, Y, X);
        v = fmaf(g0, ldz_g(src, Y, X - 2), v);
        v = fmaf(g1, ldz_g(src, Y, X - 1), v);
        v = fmaf(g3, ldz_g(src, Y, X + 1), v);
        v = fmaf(g4, ldz_g(src, Y, X + 2), v);
        sm.u.hbuf[c][r][s] = v;
    }
    __syncthreads();

    // A2 scalar: 3888 tasks = 3 x 36 x 36; zero outside image
    for (int t = tid; t < 3888; t += 256) {
        const int c = t / 1296, rem = t - c * 1296;
        const int r = rem / 36, s = rem - r * 36;
        const int Y = by0 - 2 + r, X = bx0 - 2 + s;
        float v = 0.0f;
        if (Y >= 0 && Y < IMG_H && X >= 0 && X < IMG_W) {
            v = g0 * sm.u.hbuf[c][r][s];
            v = fmaf(g1, sm.u.hbuf[c][r + 1][s], v);
            v = fmaf(g2, sm.u.hbuf[c][r + 2][s], v);
            v = fmaf(g3, sm.u.hbuf[c][r + 3][s], v);
            v = fmaf(g4, sm.u.hbuf[c][r + 4][s], v);
        }
        sm.sblur[c][r][s + 4] = v;
    }
    __syncthreads();
}

template <bool BORDER>
__device__ __forceinline__ void canny_tail(
    Smem& sm, int bx0, int by0, int tid,
    float* __restrict__ blurred_out, float* __restrict__ mag_out,
    float* __restrict__ orient_out, float* __restrict__ early_out,
    float* __restrict__ thin_out, float* __restrict__ thresh_out) {

    // ---- blurred output (reads valid after A2 barrier) ----
    {
        const int r = tid >> 3, g = tid & 7;
#pragma unroll
        for (int c = 0; c < 3; c++) {
            float4 o;
            o.x = sm.sblur[c][r + 2][4 * g + 6];
            o.y = sm.sblur[c][r + 2][4 * g + 7];
            o.z = sm.sblur[c][r + 2][4 * g + 8];
            o.w = sm.sblur[c][r + 2][4 * g + 9];
            *(float4*)&blurred_out[c * HW + (by0 + r) * IMG_W + bx0 + 4 * g] = o;
        }
    }

    // ---- Stage B ----
    if (!BORDER) {
        b_task(sm, tid);
        if (tid < 50) b_task(sm, tid + 256);
    } else {
        // scalar: 1156 tasks = 34 x 34
        for (int t = tid; t < 1156; t += 256) {
            const int r = t / 34, s = t - 34 * r;
            const int Y = by0 - 1 + r, X = bx0 - 1 + s;
            float m = 0.0f, sgx = 0.0f, sgy = 0.0f;
            if (Y >= 0 && Y < IMG_H && X >= 0 && X < IMG_W) {
#pragma unroll
                for (int c = 0; c < 3; c++) {
                    const float a  = sm.sblur[c][r][s + 4];
                    const float b  = sm.sblur[c][r][s + 5];
                    const float cc = sm.sblur[c][r][s + 6];
                    const float d  = sm.sblur[c][r + 1][s + 4];
                    const float e  = sm.sblur[c][r + 1][s + 6];
                    const float f  = sm.sblur[c][r + 2][s + 4];
                    const float gg = sm.sblur[c][r + 2][s + 5];
                    const float h  = sm.sblur[c][r + 2][s + 6];
                    const float gx = (a - cc) + 2.0f * (d - e) + (f - h);
                    const float gy = (a + 2.0f * b + cc) - (f + 2.0f * gg + h);
                    m += sqrt_approx(fmaf(gx, gx, gy * gy));
                    sgx += gx;
                    sgy += gy;
                }
            }
            sm.u.b.smag[r][s + 4] = m;
            if (r >= 1 && r < 33 && s >= 1 && s < 33) {
                sm.u.b.sk[r - 1][s - 1] =
                    (signed char)orient_k_fast(sm, sgx, sgy, r - 1, s - 1);
            }
        }
    }
    __syncthreads();

    // ---- Stage C: NMS + 5 vector output stores (256 tasks exactly) ----
    {
        const int y = tid >> 3, g = tid & 7;
        const int Y = by0 + y;
        const int Xb = bx0 + 4 * g;
        float vm[4], vo[4], ve[4], vt[4], vh[4];
#pragma unroll
        for (int i = 0; i < 4; i++) {
            const int x = 4 * g + i;
            const float m = sm.u.b.smag[y + 1][x + 5];
            const int kq  = (int)sm.u.b.sk[y][x];

            vm[i] = m;
            vo[i] = 45.0f * (float)kq;
            ve[i] = (m < THRESH) ? 0.0f : m;

            const int ip  = kq & 7;
            const int in_ = (kq + 4) & 7;
            const int pdy = unpack_d(DY_PACK, ip),  pdx = unpack_d(DX_PACK, ip);
            const int ndy = unpack_d(DY_PACK, in_), ndx = unpack_d(DX_PACK, in_);

            const float npos = sm.u.b.smag[y + 1 + pdy][x + 5 + pdx];
            const float nneg = sm.u.b.smag[y + 1 + ndy][x + 5 + ndx];
            const float sel_min = fminf(m - npos, m - nneg);

            bool is_max;
            const float eps = 4e-6f * fmaxf(m, 1.0f);
            if (fabsf(sel_min) > eps) {
                is_max = sel_min > 0.0f;
            } else {
                const double md = mag_exact_smem(sm.sblur, y, x, Y, Xb + i);
                const double dp = md - mag_exact_smem(sm.sblur, y + pdy, x + pdx,
                                                      Y + pdy, Xb + i + pdx);
                const double dn = md - mag_exact_smem(sm.sblur, y + ndy, x + ndx,
                                                      Y + ndy, Xb + i + ndx);
                is_max = fmin(dp, dn) > 0.0;
            }

            const float thin = is_max ? m : 0.0f;
            vt[i] = thin;
            vh[i] = (thin < THRESH) ? 0.0f : thin;
        }
        const int idx = Y * IMG_W + Xb;
        *(float4*)&mag_out[idx]    = make_float4(vm[0], vm[1], vm[2], vm[3]);
        *(float4*)&orient_out[idx] = make_float4(vo[0], vo[1], vo[2], vo[3]);
        *(float4*)&early_out[idx]  = make_float4(ve[0], ve[1], ve[2], ve[3]);
        *(float4*)&thin_out[idx]   = make_float4(vt[0], vt[1], vt[2], vt[3]);
        *(float4*)&thresh_out[idx] = make_float4(vh[0], vh[1], vh[2], vh[3]);
    }
}

__global__ void __launch_bounds__(256, 6)
canny_fused(const float* __restrict__ img,
            const float* __restrict__ g5,
            float* __restrict__ blurred_out,
            float* __restrict__ mag_out,
            float* __restrict__ orient_out,
            float* __restrict__ early_out,
            float* __restrict__ thin_out,
            float* __restrict__ thresh_out) {
    __shared__ Smem sm;

    const int tid = threadIdx.x;
    const int bx0 = blockIdx.x * 32;
    const int by0 = blockIdx.y * 32;

    const float g0 = __ldg(g5 + 0), g1 = __ldg(g5 + 1), g2 = __ldg(g5 + 2),
                g3 = __ldg(g5 + 3), g4 = __ldg(g5 + 4);

    const bool interior = (bx0 != 0) && (bx0 != IMG_W - 32) &&
                          (by0 != 0) && (by0 != IMG_H - 32);
    if (interior) {
        // A1: 1080 tasks, fixed-trip unrolled for ILP/MLP
        a1_task(sm, img, g0, g1, g2, g3, g4, bx0, by0, tid);
        a1_task(sm, img, g0, g1, g2, g3, g4, bx0, by0, tid + 256);
        a1_task(sm, img, g0, g1, g2, g3, g4, bx0, by0, tid + 512);
        a1_task(sm, img, g0, g1, g2, g3, g4, bx0, by0, tid + 768);
        if (tid < 56) a1_task(sm, img, g0, g1, g2, g3, g4, bx0, by0, tid + 1024);
        __syncthreads();

        // A2: 972 tasks
        a2_task(sm, g0, g1, g2, g3, g4, tid);
        a2_task(sm, g0, g1, g2, g3, g4, tid + 256);
        a2_task(sm, g0, g1, g2, g3, g4, tid + 512);
        if (tid < 204) a2_task(sm, g0, g1, g2, g3, g4, tid + 768);
        __syncthreads();

        canny_tail<false>(sm, bx0, by0, tid, blurred_out, mag_out, orient_out,
                          early_out, thin_out, thresh_out);
    } else {
        body_border(sm, img, g0, g1, g2, g3, g4, bx0, by0, tid);
        canny_tail<true>(sm, bx0, by0, tid, blurred_out, mag_out, orient_out,
                         early_out, thin_out, thresh_out);
    }
}

// ---------------------------------------------------------------------------
// Output layout (concatenated reference tuple, fp32):
//   [0,3HW) blurred | [3HW,4HW) mag | [4HW,5HW) orient | [5HW,6HW) thin
//   [6HW,7HW) thresholded | [7HW,8HW) early
// ---------------------------------------------------------------------------
extern "C" void kernel_launch(void* const* d_in, const int* in_sizes, int n_in,
                              void* d_out, int out_size) {
    const float* img  = (const float*)d_in[0];
    const float* gh_w = (const float*)d_in[1];

    float* out      = (float*)d_out;
    float* blurred  = out;
    float* mag      = out + 3 * (size_t)HW;
    float* orient   = out + 4 * (size_t)HW;
    float* thin     = out + 5 * (size_t)HW;
    float* threshed = out + 6 * (size_t)HW;
    float* early    = out + 7 * (size_t)HW;

    dim3 block(256, 1, 1);
    dim3 grid(IMG_W / 32, IMG_H / 32, 1);
    canny_fused<<<grid, block>>>(img, gh_w, blurred, mag, orient, early,
                                 thin, threshed);
}